// round 14
// baseline (speedup 1.0000x reference)
#include <cuda_runtime.h>
#include <cuda_bf16.h>
#include <math.h>

// ---------------- static problem constants ----------------
#define BATCH   64
#define NTOT    3137          // 56*56+1
#define CIN     96
#define COUT    192
#define NHEAD   2
#define HDIM    96
#define HFS     56
#define QH      28
#define KH      14
#define NQ      785           // 28*28+1
#define NK      197           // 14*14+1
#define MQ      (BATCH * NQ)  // 50240
#define MK      (BATCH * NK)  // 12608
#define SCALE   0.10206207261596577f   // 96^-0.5
#define LOG2E   1.4426950408889634f

#define QPB     (MQ / 8)      // 6280 q-pool blocks
#define KPB     (MK / 8)      // 1576 fused kv-pool blocks

typedef unsigned long long u64;
typedef unsigned int u32;
typedef unsigned short u16;

__device__ __forceinline__ u32 bf2(float lo, float hi) {
    u32 r; asm("cvt.rn.bf16x2.f32 %0, %1, %2;" : "=r"(r) : "f"(hi), "f"(lo)); return r;
}
__device__ __forceinline__ u16 bf1(float v) {
    u16 r; asm("cvt.rn.bf16.f32 %0, %1;" : "=h"(r) : "f"(v)); return r;
}
__device__ __forceinline__ float bfback(u16 h) {
    return __uint_as_float(((u32)h) << 16);
}
__device__ __forceinline__ float ex2(float x) {
    float y; asm("ex2.approx.f32 %0, %1;" : "=f"(y) : "f"(x)); return y;
}
__device__ __forceinline__ void mma_bf16(float* d, const u32* a, u32 b0, u32 b1) {
    asm volatile("mma.sync.aligned.m16n8k16.row.col.f32.bf16.bf16.f32 "
        "{%0,%1,%2,%3},{%4,%5,%6,%7},{%8,%9},{%0,%1,%2,%3};"
        : "+f"(d[0]), "+f"(d[1]), "+f"(d[2]), "+f"(d[3])
        : "r"(a[0]), "r"(a[1]), "r"(a[2]), "r"(a[3]), "r"(b0), "r"(b1));
}

// ---------------- scratch (device globals) ----------------
__device__ u16  g_qh[MQ * CIN];
__device__ u16  g_ql[MQ * CIN];
__device__ u16  g_kh[MK * CIN];
__device__ u16  g_kl[MK * CIN];
__device__ u16  g_vh[MK * CIN];
__device__ u16  g_vl[MK * CIN];
__device__ float g_qp[MQ * COUT];
__device__ float g_kp[MK * COUT];
__device__ float g_vp[MK * COUT];
__device__ u32  g_qb[MQ * 96];                       // projected q, bf16 pairs (A-frag layout)
__device__ u32  g_ehwb[BATCH * NHEAD * 784 * 14];    // eh|ew bias, bf16 pairs, log2e-scaled
// W split: [weight][term hi/lo][192 rows(n) x 48 u32 (k-pairs), LDS.128-permuted]
__device__ __align__(16) u32 g_Wt[3][2][192 * 48];

// =====================================================================
// q pool: one token per warp + LN + bf16 hi/lo split stores
// =====================================================================
__device__ __forceinline__ void pool_token_q(
    const float* __restrict__ hs, const float* __restrict__ pw,
    const float* __restrict__ gam, const float* __restrict__ bet,
    int tok)
{
    int lane = threadIdx.x & 31;
    int b = tok / NQ;
    int t = tok - b * NQ;

    float v0 = 0.f, v1 = 0.f, v2 = 0.f;
    if (t == 0) {
        const float* p = hs + (size_t)b * NTOT * CIN;
        v0 = p[lane]; v1 = p[lane + 32]; v2 = p[lane + 64];
    } else {
        int s   = t - 1;
        int y   = s / QH, x = s - y * QH;
        int iy0 = y * 2 - 1, ix0 = x * 2 - 1;
        #pragma unroll
        for (int dy = 0; dy < 3; dy++) {
            int iy = iy0 + dy;
            if (iy < 0 || iy >= HFS) continue;
            #pragma unroll
            for (int dx = 0; dx < 3; dx++) {
                int ix = ix0 + dx;
                if (ix < 0 || ix >= HFS) continue;
                const float* p = hs + ((size_t)b * NTOT + 1 + iy * HFS + ix) * CIN;
                int w = dy * 3 + dx;
                v0 += pw[(lane)      * 9 + w] * p[lane];
                v1 += pw[(lane + 32) * 9 + w] * p[lane + 32];
                v2 += pw[(lane + 64) * 9 + w] * p[lane + 64];
            }
        }
    }
    float su  = v0 + v1 + v2;
    float sq  = v0 * v0 + v1 * v1 + v2 * v2;
    #pragma unroll
    for (int o = 16; o; o >>= 1) {
        su += __shfl_xor_sync(0xffffffffu, su, o);
        sq += __shfl_xor_sync(0xffffffffu, sq, o);
    }
    float mean = su * (1.f / 96.f);
    float rs   = rsqrtf(sq * (1.f / 96.f) - mean * mean + 1e-5f);
    float y0 = (v0 - mean) * rs * gam[lane]      + bet[lane];
    float y1 = (v1 - mean) * rs * gam[lane + 32] + bet[lane + 32];
    float y2 = (v2 - mean) * rs * gam[lane + 64] + bet[lane + 64];
    size_t base = (size_t)tok * CIN;
    u16 h;
    h = bf1(y0); g_qh[base + lane]      = h; g_ql[base + lane]      = bf1(y0 - bfback(h));
    h = bf1(y1); g_qh[base + lane + 32] = h; g_ql[base + lane + 32] = bf1(y1 - bfback(h));
    h = bf1(y2); g_qh[base + lane + 64] = h; g_ql[base + lane + 64] = bf1(y2 - bfback(h));
}

// =====================================================================
// fused k+v pool: one token per warp, shared input loads, two LNs
// =====================================================================
__device__ __forceinline__ void pool_token_kv(
    const float* __restrict__ hs,
    const float* __restrict__ pwk, const float* __restrict__ gk, const float* __restrict__ bk,
    const float* __restrict__ pwv, const float* __restrict__ gv, const float* __restrict__ bv,
    int tok)
{
    int lane = threadIdx.x & 31;
    int b = tok / NK;
    int t = tok - b * NK;

    float a0 = 0.f, a1 = 0.f, a2 = 0.f;   // k
    float c0 = 0.f, c1 = 0.f, c2 = 0.f;   // v
    if (t == 0) {
        const float* p = hs + (size_t)b * NTOT * CIN;
        a0 = c0 = p[lane]; a1 = c1 = p[lane + 32]; a2 = c2 = p[lane + 64];
    } else {
        int s   = t - 1;
        int y   = s / KH, x = s - y * KH;
        int iy0 = y * 4 - 1, ix0 = x * 4 - 1;
        #pragma unroll
        for (int dy = 0; dy < 3; dy++) {
            int iy = iy0 + dy;
            if (iy < 0 || iy >= HFS) continue;
            #pragma unroll
            for (int dx = 0; dx < 3; dx++) {
                int ix = ix0 + dx;
                if (ix < 0 || ix >= HFS) continue;
                const float* p = hs + ((size_t)b * NTOT + 1 + iy * HFS + ix) * CIN;
                int w = dy * 3 + dx;
                float p0 = p[lane], p1 = p[lane + 32], p2 = p[lane + 64];
                a0 += pwk[(lane)      * 9 + w] * p0;
                a1 += pwk[(lane + 32) * 9 + w] * p1;
                a2 += pwk[(lane + 64) * 9 + w] * p2;
                c0 += pwv[(lane)      * 9 + w] * p0;
                c1 += pwv[(lane + 32) * 9 + w] * p1;
                c2 += pwv[(lane + 64) * 9 + w] * p2;
            }
        }
    }
    size_t base = (size_t)tok * CIN;
    {
        float su = a0 + a1 + a2, sq = a0 * a0 + a1 * a1 + a2 * a2;
        #pragma unroll
        for (int o = 16; o; o >>= 1) {
            su += __shfl_xor_sync(0xffffffffu, su, o);
            sq += __shfl_xor_sync(0xffffffffu, sq, o);
        }
        float mean = su * (1.f / 96.f);
        float rs = rsqrtf(sq * (1.f / 96.f) - mean * mean + 1e-5f);
        float y0 = (a0 - mean) * rs * gk[lane]      + bk[lane];
        float y1 = (a1 - mean) * rs * gk[lane + 32] + bk[lane + 32];
        float y2 = (a2 - mean) * rs * gk[lane + 64] + bk[lane + 64];
        u16 h;
        h = bf1(y0); g_kh[base + lane]      = h; g_kl[base + lane]      = bf1(y0 - bfback(h));
        h = bf1(y1); g_kh[base + lane + 32] = h; g_kl[base + lane + 32] = bf1(y1 - bfback(h));
        h = bf1(y2); g_kh[base + lane + 64] = h; g_kl[base + lane + 64] = bf1(y2 - bfback(h));
    }
    {
        float su = c0 + c1 + c2, sq = c0 * c0 + c1 * c1 + c2 * c2;
        #pragma unroll
        for (int o = 16; o; o >>= 1) {
            su += __shfl_xor_sync(0xffffffffu, su, o);
            sq += __shfl_xor_sync(0xffffffffu, sq, o);
        }
        float mean = su * (1.f / 96.f);
        float rs = rsqrtf(sq * (1.f / 96.f) - mean * mean + 1e-5f);
        float y0 = (c0 - mean) * rs * gv[lane]      + bv[lane];
        float y1 = (c1 - mean) * rs * gv[lane + 32] + bv[lane + 32];
        float y2 = (c2 - mean) * rs * gv[lane + 64] + bv[lane + 64];
        u16 h;
        h = bf1(y0); g_vh[base + lane]      = h; g_vl[base + lane]      = bf1(y0 - bfback(h));
        h = bf1(y1); g_vh[base + lane + 32] = h; g_vl[base + lane + 32] = bf1(y1 - bfback(h));
        h = bf1(y2); g_vh[base + lane + 64] = h; g_vl[base + lane + 64] = bf1(y2 - bfback(h));
    }
}

// =====================================================================
// Kernel A: q pools + fused kv pools + weight split (blockIdx ranges)
// =====================================================================
__global__ __launch_bounds__(256)
void pre_kernel(const float* __restrict__ hs,
                const float* __restrict__ pqw, const float* __restrict__ gq, const float* __restrict__ betaq,
                const float* __restrict__ pkw, const float* __restrict__ gk, const float* __restrict__ betak,
                const float* __restrict__ pvw, const float* __restrict__ gv, const float* __restrict__ betav,
                const float* __restrict__ Wq, const float* __restrict__ Wk, const float* __restrict__ Wv)
{
    int bid  = blockIdx.x;
    int warp = threadIdx.x >> 5;
    if (bid < QPB) {
        pool_token_q(hs, pqw, gq, betaq, bid * 8 + warp);
    } else if (bid < QPB + KPB) {
        pool_token_kv(hs, pkw, gk, betak, pvw, gv, betav, (bid - QPB) * 8 + warp);
    } else {
        int widx = bid - (QPB + KPB);
        const float* W = (widx == 0) ? Wq : (widx == 1) ? Wk : Wv;
        u32* outh = g_Wt[widx][0];
        u32* outl = g_Wt[widx][1];
        for (int i = threadIdx.x; i < 192 * 48; i += 256) {
            int n = i / 48, w = i - n * 48;
            float f0 = W[(2 * w)     * 192 + n];
            float f1 = W[(2 * w + 1) * 192 + n];
            u16 h0 = bf1(f0); u16 l0 = bf1(f0 - bfback(h0));
            u16 h1 = bf1(f1); u16 l1 = bf1(f1 - bfback(h1));
            int pos = n * 48 + (w & 3) * 12 + (w >> 2);
            outh[pos] = (u32)h0 | ((u32)h1 << 16);
            outl[pos] = (u32)l0 | ((u32)l1 << 16);
        }
    }
}

// =====================================================================
// Kernel B: fused q/k/v projection via bf16-split tensor cores.
// For q, additionally emit bf16-pair copy g_qb (A-fragment word layout).
// =====================================================================
#define QJB 393   // (MQ+127)/128
#define KJB 99    // (MK+127)/128
#define PROJ_SMEM (2 * 192 * 48 * 4)   // 73728
__global__ __launch_bounds__(256, 2)
void proj_mma_kernel(const float* __restrict__ bq,
                     const float* __restrict__ bk,
                     const float* __restrict__ bv)
{
    int bid = blockIdx.x;
    int widx, rb, M;
    const u16 *xh, *xl;
    const float* bias;
    float* Y;
    if (bid < QJB)            { widx = 0; rb = bid;             xh = g_qh; xl = g_ql; bias = bq; Y = g_qp; M = MQ; }
    else if (bid < QJB + KJB) { widx = 1; rb = bid - QJB;       xh = g_kh; xl = g_kl; bias = bk; Y = g_kp; M = MK; }
    else                      { widx = 2; rb = bid - QJB - KJB; xh = g_vh; xl = g_vl; bias = bv; Y = g_vp; M = MK; }

    extern __shared__ u32 swp[];
    u32* sWh = swp;
    u32* sWl = swp + 192 * 48;
    {
        const uint4* srcH = (const uint4*)g_Wt[widx][0];
        const uint4* srcL = (const uint4*)g_Wt[widx][1];
        uint4* dH = (uint4*)sWh;
        uint4* dL = (uint4*)sWl;
        for (int i = threadIdx.x; i < 192 * 48 / 4; i += 256) {
            dH[i] = srcH[i]; dL[i] = srcL[i];
        }
    }
    __syncthreads();

    int warp = threadIdx.x >> 5, lane = threadIdx.x & 31;
    int g = lane >> 2, t = lane & 3;
    int r0 = rb * 128 + warp * 16 + g;
    int r1 = r0 + 8;
    int r0c = (r0 < M) ? r0 : M - 1;
    int r1c = (r1 < M) ? r1 : M - 1;

    const u32* x0h = (const u32*)(xh + (size_t)r0c * CIN);
    const u32* x1h = (const u32*)(xh + (size_t)r1c * CIN);
    const u32* x0l = (const u32*)(xl + (size_t)r0c * CIN);
    const u32* x1l = (const u32*)(xl + (size_t)r1c * CIN);

    u32 ah[6][4], al[6][4];
    #pragma unroll
    for (int ks = 0; ks < 6; ks++) {
        ah[ks][0] = x0h[8 * ks + t];     ah[ks][1] = x1h[8 * ks + t];
        ah[ks][2] = x0h[8 * ks + t + 4]; ah[ks][3] = x1h[8 * ks + t + 4];
        al[ks][0] = x0l[8 * ks + t];     al[ks][1] = x1l[8 * ks + t];
        al[ks][2] = x0l[8 * ks + t + 4]; al[ks][3] = x1l[8 * ks + t + 4];
    }

    #pragma unroll 2
    for (int nt = 0; nt < 24; nt++) {
        const uint4* hp = (const uint4*)(sWh + (8 * nt + g) * 48) + t * 3;
        const uint4* lp = (const uint4*)(sWl + (8 * nt + g) * 48) + t * 3;
        uint4 H0 = hp[0], H1 = hp[1], H2 = hp[2];
        uint4 L0 = lp[0], L1 = lp[1], L2 = lp[2];
        float aA[4] = {0.f, 0.f, 0.f, 0.f};
        float aB[4] = {0.f, 0.f, 0.f, 0.f};
        mma_bf16(aA, ah[0], H0.x, H0.y); mma_bf16(aB, al[0], H0.x, H0.y);
        mma_bf16(aA, ah[1], H0.z, H0.w); mma_bf16(aB, al[1], H0.z, H0.w);
        mma_bf16(aA, ah[2], H1.x, H1.y); mma_bf16(aB, al[2], H1.x, H1.y);
        mma_bf16(aA, ah[3], H1.z, H1.w); mma_bf16(aB, al[3], H1.z, H1.w);
        mma_bf16(aA, ah[4], H2.x, H2.y); mma_bf16(aB, al[4], H2.x, H2.y);
        mma_bf16(aA, ah[5], H2.z, H2.w); mma_bf16(aB, al[5], H2.z, H2.w);
        mma_bf16(aB, ah[0], L0.x, L0.y);
        mma_bf16(aB, ah[1], L0.z, L0.w);
        mma_bf16(aB, ah[2], L1.x, L1.y);
        mma_bf16(aB, ah[3], L1.z, L1.w);
        mma_bf16(aB, ah[4], L2.x, L2.y);
        mma_bf16(aB, ah[5], L2.z, L2.w);

        float2 bvv = *(const float2*)(bias + 8 * nt + 2 * t);
        float y00 = aA[0] + aB[0] + bvv.x, y01 = aA[1] + aB[1] + bvv.y;
        float y10 = aA[2] + aB[2] + bvv.x, y11 = aA[3] + aB[3] + bvv.y;
        if (r0 < M) {
            *(float2*)(Y + (size_t)r0 * COUT + 8 * nt + 2 * t) = make_float2(y00, y01);
            if (widx == 0) g_qb[(size_t)r0 * 96 + 4 * nt + t] = bf2(y00, y01);
        }
        if (r1 < M) {
            *(float2*)(Y + (size_t)r1 * COUT + 8 * nt + 2 * t) = make_float2(y10, y11);
            if (widx == 0) g_qb[(size_t)r1 * 96 + 4 * nt + t] = bf2(y10, y11);
        }
    }
}

// =====================================================================
// Kernel C: rel-pos bias via tensor cores; emits bf16 pairs (g_ehwb).
// =====================================================================
#define RELN_SMEM (112 * 48 * 4 + 8 * 16 * 112 * 4)   // 78848
__global__ __launch_bounds__(256, 2)
void rel_mma_kernel(const float* __restrict__ relh,
                    const float* __restrict__ relw)
{
    extern __shared__ u32 shm[];
    u32*   sRt = shm;                        // [112][48]
    float* sE  = (float*)(shm + 112 * 48);   // per-warp [16][112]

    int bid  = blockIdx.x;
    int bh   = bid >> 1, half = bid & 1;
    int b    = bh >> 1, head = bh & 1;
    int tid  = threadIdx.x;
    int warp = tid >> 5, lane = tid & 31;
    int g = lane >> 2, t = lane & 3;

    for (int i = tid; i < 112 * 48; i += 256) {
        int n = i / 48, w = i - n * 48;
        float r0 = 0.f, r1 = 0.f;
        if (n < 55)       { r0 = relh[n * 96 + 2 * w];        r1 = relh[n * 96 + 2 * w + 1]; }
        else if (n < 110) { r0 = relw[(n - 55) * 96 + 2 * w]; r1 = relw[(n - 55) * 96 + 2 * w + 1]; }
        sRt[n * 48 + (w & 3) * 12 + (w >> 2)] = bf2(r0 * LOG2E, r1 * LOG2E);
    }
    __syncthreads();

    const float* qbase = g_qp + (size_t)b * NQ * COUT + head * HDIM;
    float* myE = sE + warp * (16 * 112);
    int mEnd = (half == 0) ? 25 : 49;

    for (int m = half * 25 + warp; m < mEnd; m += 8) {
        int s0 = m * 16 + g;
        const float* q0 = qbase + (size_t)(s0 + 1) * COUT;
        const float* q1 = qbase + (size_t)(s0 + 9) * COUT;

        u32 a[6][4];
        #pragma unroll
        for (int ks = 0; ks < 6; ks++) {
            float2 x0 = *(const float2*)(q0 + 16 * ks + 2 * t);
            float2 x1 = *(const float2*)(q1 + 16 * ks + 2 * t);
            float2 x2 = *(const float2*)(q0 + 16 * ks + 2 * t + 8);
            float2 x3 = *(const float2*)(q1 + 16 * ks + 2 * t + 8);
            a[ks][0] = bf2(x0.x, x0.y);
            a[ks][1] = bf2(x1.x, x1.y);
            a[ks][2] = bf2(x2.x, x2.y);
            a[ks][3] = bf2(x3.x, x3.y);
        }

        #pragma unroll
        for (int nt = 0; nt < 14; nt++) {
            const uint4* rp = (const uint4*)(sRt + (8 * nt + g) * 48) + t * 3;
            uint4 R0 = rp[0], R1 = rp[1], R2 = rp[2];
            float acc[4] = {0.f, 0.f, 0.f, 0.f};
            mma_bf16(acc, a[0], R0.x, R0.y); mma_bf16(acc, a[1], R0.z, R0.w);
            mma_bf16(acc, a[2], R1.x, R1.y); mma_bf16(acc, a[3], R1.z, R1.w);
            mma_bf16(acc, a[4], R2.x, R2.y); mma_bf16(acc, a[5], R2.z, R2.w);
            *(float2*)(myE + g * 112 + 8 * nt + 2 * t)       = make_float2(acc[0], acc[1]);
            *(float2*)(myE + (g + 8) * 112 + 8 * nt + 2 * t) = make_float2(acc[2], acc[3]);
        }
        __syncwarp();

        // gather -> bf16 pairs; 16 rows x 14 words = 224 words, linear STG
        int sbase = m * 16;
        u32* outp = g_ehwb + ((size_t)bh * 784 + sbase) * 14;
        #pragma unroll
        for (int it = 0; it < 7; it++) {
            int idx = lane + 32 * it;
            int r = idx / 14, w = idx - r * 14;
            int s = sbase + r;
            int qy = s / 28, qx = s - qy * 28;
            int k0 = 2 * w, k1 = 2 * w + 1;
            int col0 = (k0 < 14) ? (qy - 2 * k0 + 26) : (55 + qx - 2 * (k0 - 14) + 26);
            int col1 = (k1 < 14) ? (qy - 2 * k1 + 26) : (55 + qx - 2 * (k1 - 14) + 26);
            outp[idx] = bf2(myE[r * 112 + col0], myE[r * 112 + col1]);
        }
        __syncwarp();
    }
}

// =====================================================================
// Kernel D: fused attention — grid 128, 512 threads (round-11 config);
// Q and bias fragments loaded as pre-packed bf16 words (no cvt).
// =====================================================================
#define SK_OFF   0
#define SVT_OFF  54400
#define ATTN_SMEM 98944

__global__ __launch_bounds__(512, 1)
void attn_kernel(float* __restrict__ out)
{
    extern __shared__ char smem[];
    u32* sK32 = (u32*)(smem + SK_OFF);
    u32* sV32 = (u32*)(smem + SVT_OFF);
    int bh   = blockIdx.x;
    int b    = bh >> 1, head = bh & 1;
    int tid  = threadIdx.x;
    int warp = tid >> 5, lane = tid & 31;
    int g = lane >> 2, t = lane & 3;

    const float SC2 = SCALE * LOG2E;

    // ---- staging (once per bh) ----
    for (int i = tid; i < 200 * 64; i += 512) {
        int j = i >> 6, c2 = i & 63;
        u32 val = 0;
        if (j < NK) {
            if (c2 < 48) {
                const float* kp = g_kp + ((size_t)b * NK + j) * COUT + head * HDIM + 2 * c2;
                val = bf2(SC2 * kp[0], SC2 * kp[1]);
            } else if (j >= 1) {
                int ky = (j - 1) / 14, kx = (j - 1) - 14 * ky;
                int i0 = 2 * (c2 - 48);
                int i1 = i0 + 1;
                bool lo = (i0 < 14) ? (i0 == ky) : ((i0 < 28) && (i0 - 14 == kx));
                bool hi = (i1 < 14) ? (i1 == ky) : ((i1 < 28) && (i1 - 14 == kx));
                val = (lo ? 0x3F80u : 0u) | (hi ? 0x3F800000u : 0u);
            }
        }
        sK32[j * 68 + (c2 & 3) * 16 + (c2 >> 2)] = val;
    }
    for (int i = tid; i < 108 * 96; i += 512) {
        int w = i / 96, c = i - w * 96;
        int j0 = 2 * w;
        const float* vp = g_vp + ((size_t)b * NK + j0) * COUT + head * HDIM + c;
        float v0 = (j0     < NK) ? vp[0]    : 0.f;
        float v1 = (j0 + 1 < NK) ? vp[COUT] : 0.f;
        sV32[c * 116 + (w & 3) * 28 + (w >> 2)] = bf2(v0, v1);
    }
    __syncthreads();

    const float* qbase = g_qp + (size_t)b * NQ * COUT + head * HDIM;
    const u32*   qbb   = g_qb + (size_t)b * NQ * 96 + head * 48;   // FIXED: batch offset
    const u32*   ebase = g_ehwb + (size_t)bh * 784 * 14;

    for (int tile = warp; tile < 50; tile += 16) {
        int q0 = tile * 16;
        int r0 = q0 + g, r1 = r0 + 8;
        int r0c = (r0 < NQ) ? r0 : NQ - 1;
        int r1c = (r1 < NQ) ? r1 : NQ - 1;

        // ---- Q A-fragments: pre-packed bf16 words ----
        const u32* q_r0 = qbb + (size_t)r0c * 96;
        const u32* q_r1 = qbb + (size_t)r1c * 96;
        u32 a[8][4];
        #pragma unroll
        for (int ks = 0; ks < 6; ks++) {
            a[ks][0] = q_r0[8 * ks + t];
            a[ks][1] = q_r1[8 * ks + t];
            a[ks][2] = q_r0[8 * ks + t + 4];
            a[ks][3] = q_r1[8 * ks + t + 4];
        }
        {
            bool v0ok = (r0 >= 1 && r0 < NQ);
            bool v1ok = (r1 >= 1 && r1 < NQ);
            const u32* e0 = ebase + (size_t)(v0ok ? r0 - 1 : 0) * 14;
            const u32* e1 = ebase + (size_t)(v1ok ? r1 - 1 : 0) * 14;
            a[6][0] = v0ok ? e0[t]     : 0u;
            a[6][1] = v1ok ? e1[t]     : 0u;
            a[6][2] = v0ok ? e0[4 + t] : 0u;
            a[6][3] = v1ok ? e1[4 + t] : 0u;
            a[7][0] = v0ok ? e0[8 + t] : 0u;
            a[7][1] = v1ok ? e1[8 + t] : 0u;
            a[7][2] = (v0ok && t < 2) ? e0[12 + t] : 0u;
            a[7][3] = (v1ok && t < 2) ? e1[12 + t] : 0u;
        }

        float o[12][4];
        #pragma unroll
        for (int nt = 0; nt < 12; nt++)
            #pragma unroll
            for (int i = 0; i < 4; i++) o[nt][i] = 0.f;
        float slo = 0.f, shi = 0.f;

        #pragma unroll
        for (int ch = 0; ch < 6; ch++) {
            float acc[4][4];
            #pragma unroll
            for (int nt = 0; nt < 4; nt++)
                #pragma unroll
                for (int i = 0; i < 4; i++) acc[nt][i] = 0.f;

            #pragma unroll
            for (int nt2 = 0; nt2 < 4; nt2++) {
                int nt = 4 * ch + nt2;
                const uint4* kp = (const uint4*)(sK32 + (8 * nt + g) * 68 + t * 16);
                uint4 K0 = kp[0], K1 = kp[1], K2 = kp[2], K3 = kp[3];
                float* d = acc[nt2];
                mma_bf16(d, a[0], K0.x, K0.y); mma_bf16(d, a[1], K0.z, K0.w);
                mma_bf16(d, a[2], K1.x, K1.y); mma_bf16(d, a[3], K1.z, K1.w);
                mma_bf16(d, a[4], K2.x, K2.y); mma_bf16(d, a[5], K2.z, K2.w);
                mma_bf16(d, a[6], K3.x, K3.y); mma_bf16(d, a[7], K3.z, K3.w);
            }

            u32 pa[2][4];
            #pragma unroll
            for (int ks2 = 0; ks2 < 2; ks2++) {
                float e00 = ex2(acc[2 * ks2][0]),     e01 = ex2(acc[2 * ks2][1]);
                float e02 = ex2(acc[2 * ks2][2]),     e03 = ex2(acc[2 * ks2][3]);
                float e10 = ex2(acc[2 * ks2 + 1][0]), e11 = ex2(acc[2 * ks2 + 1][1]);
                float e12 = ex2(acc[2 * ks2 + 1][2]), e13 = ex2(acc[2 * ks2 + 1][3]);
                slo += e00 + e01 + e10 + e11;
                shi += e02 + e03 + e12 + e13;
                pa[ks2][0] = bf2(e00, e01); pa[ks2][1] = bf2(e02, e03);
                pa[ks2][2] = bf2(e10, e11); pa[ks2][3] = bf2(e12, e13);
            }

            #pragma unroll
            for (int nt = 0; nt < 12; nt++) {
                const uint4* vp = (const uint4*)(sV32 + (8 * nt + g) * 116 + t * 28 + ch * 4);
                uint4 V = vp[0];
                float* d = o[nt];
                mma_bf16(d, pa[0], V.x, V.y);
                mma_bf16(d, pa[1], V.z, V.w);
            }
        }

        // ---- tail n-tile 24 (j = 192..196) ----
        {
            float at[4] = {0.f, 0.f, 0.f, 0.f};
            const uint4* kp = (const uint4*)(sK32 + (192 + g) * 68 + t * 16);
            uint4 K0 = kp[0], K1 = kp[1], K2 = kp[2], K3 = kp[3];
            mma_bf16(at, a[0], K0.x, K0.y); mma_bf16(at, a[1], K0.z, K0.w);
            mma_bf16(at, a[2], K1.x, K1.y); mma_bf16(at, a[3], K1.z, K1.w);
            mma_bf16(at, a[4], K2.x, K2.y); mma_bf16(at, a[5], K2.z, K2.w);
            mma_bf16(at, a[6], K3.x, K3.y); mma_bf16(at, a[7], K3.z, K3.w);
            int j0 = 192 + 2 * t;
            float e0 = (j0     < NK) ? ex2(at[0]) : 0.f;
            float e1 = (j0 + 1 < NK) ? ex2(at[1]) : 0.f;
            float e2 = (j0     < NK) ? ex2(at[2]) : 0.f;
            float e3 = (j0 + 1 < NK) ? ex2(at[3]) : 0.f;
            slo += e0 + e1; shi += e2 + e3;
            u32 paT[4] = { bf2(e0, e1), bf2(e2, e3), 0u, 0u };
            #pragma unroll
            for (int nt = 0; nt < 12; nt++) {
                uint4 V = *(const uint4*)(sV32 + (8 * nt + g) * 116 + t * 28 + 24);
                mma_bf16(o[nt], paT, V.x, V.y);
            }
        }

        slo += __shfl_xor_sync(0xffffffffu, slo, 1);
        slo += __shfl_xor_sync(0xffffffffu, slo, 2);
        shi += __shfl_xor_sync(0xffffffffu, shi, 1);
        shi += __shfl_xor_sync(0xffffffffu, shi, 2);
        float ilo = 1.f / slo, ihi = 1.f / shi;

        float* obase = out + (size_t)b * NQ * COUT + head * HDIM;
        #pragma unroll
        for (int nt = 0; nt < 12; nt++) {
            int c = 8 * nt + 2 * t;
            if (r0 < NQ) {
                float2 r = make_float2(o[nt][0] * ilo, o[nt][1] * ilo);
                if (r0 >= 1) {
                    float2 q = *(const float2*)(qbase + (size_t)r0 * COUT + c);
                    r.x += q.x; r.y += q.y;
                }
                *(float2*)(obase + (size_t)r0 * COUT + c) = r;
            }
            if (r1 < NQ) {
                float2 r = make_float2(o[nt][2] * ihi, o[nt][3] * ihi);
                if (r1 >= 1) {
                    float2 q = *(const float2*)(qbase + (size_t)r1 * COUT + c);
                    r.x += q.x; r.y += q.y;
                }
                *(float2*)(obase + (size_t)r1 * COUT + c) = r;
            }
        }
    }
}

// =====================================================================
// launch: pre -> proj -> rel -> attn
// =====================================================================
extern "C" void kernel_launch(void* const* d_in, const int* in_sizes, int n_in,
                              void* d_out, int out_size)
{
    const float* hs    = (const float*)d_in[0];
    const float* Wq    = (const float*)d_in[1];
    const float* bq    = (const float*)d_in[2];
    const float* Wk    = (const float*)d_in[3];
    const float* bk    = (const float*)d_in[4];
    const float* Wv    = (const float*)d_in[5];
    const float* bv    = (const float*)d_in[6];
    const float* pqw   = (const float*)d_in[7];
    const float* pkw   = (const float*)d_in[8];
    const float* pvw   = (const float*)d_in[9];
    const float* gq    = (const float*)d_in[10];
    const float* betaq = (const float*)d_in[11];
    const float* gk    = (const float*)d_in[12];
    const float* betak = (const float*)d_in[13];
    const float* gv    = (const float*)d_in[14];
    const float* betav = (const float*)d_in[15];
    const float* relh  = (const float*)d_in[16];
    const float* relw  = (const float*)d_in[17];
    float* out = (float*)d_out;

    cudaFuncSetAttribute(proj_mma_kernel, cudaFuncAttributeMaxDynamicSharedMemorySize, PROJ_SMEM);
    cudaFuncSetAttribute(rel_mma_kernel, cudaFuncAttributeMaxDynamicSharedMemorySize, RELN_SMEM);
    cudaFuncSetAttribute(attn_kernel,  cudaFuncAttributeMaxDynamicSharedMemorySize, ATTN_SMEM);

    // A: q pools + fused kv pools + weight split
    pre_kernel<<<QPB + KPB + 3, 256>>>(hs,
        pqw, gq, betaq, pkw, gk, betak, pvw, gv, betav, Wq, Wk, Wv);

    // B: all three projections (+ bf16 q copy)
    proj_mma_kernel<<<QJB + 2 * KJB, 256, PROJ_SMEM>>>(bq, bk, bv);

    // C: rel-pos bias via tensor cores (bf16-pair output)
    rel_mma_kernel<<<BATCH * NHEAD * 2, 256, RELN_SMEM>>>(relh, relw);

    // D: fused tensor-core attention (512 threads, pre-packed fragments)
    attn_kernel<<<BATCH * NHEAD, 512, ATTN_SMEM>>>(out);
}

// round 15
// speedup vs baseline: 1.0993x; 1.0993x over previous
#include <cuda_runtime.h>
#include <cuda_bf16.h>
#include <math.h>

// ---------------- static problem constants ----------------
#define BATCH   64
#define NTOT    3137          // 56*56+1
#define CIN     96
#define COUT    192
#define NHEAD   2
#define HDIM    96
#define HFS     56
#define QH      28
#define KH      14
#define NQ      785           // 28*28+1
#define NK      197           // 14*14+1
#define MQ      (BATCH * NQ)  // 50240
#define MK      (BATCH * NK)  // 12608
#define SCALE   0.10206207261596577f   // 96^-0.5
#define LOG2E   1.4426950408889634f

#define QPB     (MQ / 8)      // 6280 q-pool blocks
#define KPB     (MK / 8)      // 1576 fused kv-pool blocks

typedef unsigned long long u64;
typedef unsigned int u32;
typedef unsigned short u16;

__device__ __forceinline__ u32 bf2(float lo, float hi) {
    u32 r; asm("cvt.rn.bf16x2.f32 %0, %1, %2;" : "=r"(r) : "f"(hi), "f"(lo)); return r;
}
__device__ __forceinline__ u16 bf1(float v) {
    u16 r; asm("cvt.rn.bf16.f32 %0, %1;" : "=h"(r) : "f"(v)); return r;
}
__device__ __forceinline__ float bfback(u16 h) {
    return __uint_as_float(((u32)h) << 16);
}
__device__ __forceinline__ float ex2(float x) {
    float y; asm("ex2.approx.f32 %0, %1;" : "=f"(y) : "f"(x)); return y;
}
__device__ __forceinline__ void mma_bf16(float* d, const u32* a, u32 b0, u32 b1) {
    asm volatile("mma.sync.aligned.m16n8k16.row.col.f32.bf16.bf16.f32 "
        "{%0,%1,%2,%3},{%4,%5,%6,%7},{%8,%9},{%0,%1,%2,%3};"
        : "+f"(d[0]), "+f"(d[1]), "+f"(d[2]), "+f"(d[3])
        : "r"(a[0]), "r"(a[1]), "r"(a[2]), "r"(a[3]), "r"(b0), "r"(b1));
}

// ---------------- scratch (device globals) ----------------
__device__ u16  g_qh[MQ * CIN];
__device__ u16  g_ql[MQ * CIN];
__device__ u16  g_kh[MK * CIN];
__device__ u16  g_kl[MK * CIN];
__device__ u16  g_vh[MK * CIN];
__device__ u16  g_vl[MK * CIN];
__device__ float g_qp[MQ * COUT];
__device__ float g_kp[MK * COUT];
__device__ float g_vp[MK * COUT];
__device__ float g_ehw[BATCH * NHEAD * 784 * 28];   // eh[14]|ew[14], pre-scaled by log2e
// W split: [weight][term hi/lo][192 rows(n) x 48 u32 (k-pairs), LDS.128-permuted]
__device__ __align__(16) u32 g_Wt[3][2][192 * 48];

// =====================================================================
// q pool: one token per warp + LN + bf16 hi/lo split stores
// (pw points to SHARED memory staged by the caller — conflict-free LDS)
// =====================================================================
__device__ __forceinline__ void pool_token_q(
    const float* __restrict__ hs, const float* pw,
    const float* __restrict__ gam, const float* __restrict__ bet,
    int tok)
{
    int lane = threadIdx.x & 31;
    int b = tok / NQ;
    int t = tok - b * NQ;

    float v0 = 0.f, v1 = 0.f, v2 = 0.f;
    if (t == 0) {
        const float* p = hs + (size_t)b * NTOT * CIN;
        v0 = p[lane]; v1 = p[lane + 32]; v2 = p[lane + 64];
    } else {
        int s   = t - 1;
        int y   = s / QH, x = s - y * QH;
        int iy0 = y * 2 - 1, ix0 = x * 2 - 1;
        #pragma unroll
        for (int dy = 0; dy < 3; dy++) {
            int iy = iy0 + dy;
            if (iy < 0 || iy >= HFS) continue;
            #pragma unroll
            for (int dx = 0; dx < 3; dx++) {
                int ix = ix0 + dx;
                if (ix < 0 || ix >= HFS) continue;
                const float* p = hs + ((size_t)b * NTOT + 1 + iy * HFS + ix) * CIN;
                int w = dy * 3 + dx;
                v0 += pw[(lane)      * 9 + w] * p[lane];
                v1 += pw[(lane + 32) * 9 + w] * p[lane + 32];
                v2 += pw[(lane + 64) * 9 + w] * p[lane + 64];
            }
        }
    }
    float su  = v0 + v1 + v2;
    float sq  = v0 * v0 + v1 * v1 + v2 * v2;
    #pragma unroll
    for (int o = 16; o; o >>= 1) {
        su += __shfl_xor_sync(0xffffffffu, su, o);
        sq += __shfl_xor_sync(0xffffffffu, sq, o);
    }
    float mean = su * (1.f / 96.f);
    float rs   = rsqrtf(sq * (1.f / 96.f) - mean * mean + 1e-5f);
    float y0 = (v0 - mean) * rs * gam[lane]      + bet[lane];
    float y1 = (v1 - mean) * rs * gam[lane + 32] + bet[lane + 32];
    float y2 = (v2 - mean) * rs * gam[lane + 64] + bet[lane + 64];
    size_t base = (size_t)tok * CIN;
    u16 h;
    h = bf1(y0); g_qh[base + lane]      = h; g_ql[base + lane]      = bf1(y0 - bfback(h));
    h = bf1(y1); g_qh[base + lane + 32] = h; g_ql[base + lane + 32] = bf1(y1 - bfback(h));
    h = bf1(y2); g_qh[base + lane + 64] = h; g_ql[base + lane + 64] = bf1(y2 - bfback(h));
}

// =====================================================================
// fused k+v pool: one token per warp, shared input loads, two LNs
// (pwk/pwv point to SHARED memory)
// =====================================================================
__device__ __forceinline__ void pool_token_kv(
    const float* __restrict__ hs,
    const float* pwk, const float* __restrict__ gk, const float* __restrict__ bk,
    const float* pwv, const float* __restrict__ gv, const float* __restrict__ bv,
    int tok)
{
    int lane = threadIdx.x & 31;
    int b = tok / NK;
    int t = tok - b * NK;

    float a0 = 0.f, a1 = 0.f, a2 = 0.f;   // k
    float c0 = 0.f, c1 = 0.f, c2 = 0.f;   // v
    if (t == 0) {
        const float* p = hs + (size_t)b * NTOT * CIN;
        a0 = c0 = p[lane]; a1 = c1 = p[lane + 32]; a2 = c2 = p[lane + 64];
    } else {
        int s   = t - 1;
        int y   = s / KH, x = s - y * KH;
        int iy0 = y * 4 - 1, ix0 = x * 4 - 1;
        #pragma unroll
        for (int dy = 0; dy < 3; dy++) {
            int iy = iy0 + dy;
            if (iy < 0 || iy >= HFS) continue;
            #pragma unroll
            for (int dx = 0; dx < 3; dx++) {
                int ix = ix0 + dx;
                if (ix < 0 || ix >= HFS) continue;
                const float* p = hs + ((size_t)b * NTOT + 1 + iy * HFS + ix) * CIN;
                int w = dy * 3 + dx;
                float p0 = p[lane], p1 = p[lane + 32], p2 = p[lane + 64];
                a0 += pwk[(lane)      * 9 + w] * p0;
                a1 += pwk[(lane + 32) * 9 + w] * p1;
                a2 += pwk[(lane + 64) * 9 + w] * p2;
                c0 += pwv[(lane)      * 9 + w] * p0;
                c1 += pwv[(lane + 32) * 9 + w] * p1;
                c2 += pwv[(lane + 64) * 9 + w] * p2;
            }
        }
    }
    size_t base = (size_t)tok * CIN;
    {
        float su = a0 + a1 + a2, sq = a0 * a0 + a1 * a1 + a2 * a2;
        #pragma unroll
        for (int o = 16; o; o >>= 1) {
            su += __shfl_xor_sync(0xffffffffu, su, o);
            sq += __shfl_xor_sync(0xffffffffu, sq, o);
        }
        float mean = su * (1.f / 96.f);
        float rs = rsqrtf(sq * (1.f / 96.f) - mean * mean + 1e-5f);
        float y0 = (a0 - mean) * rs * gk[lane]      + bk[lane];
        float y1 = (a1 - mean) * rs * gk[lane + 32] + bk[lane + 32];
        float y2 = (a2 - mean) * rs * gk[lane + 64] + bk[lane + 64];
        u16 h;
        h = bf1(y0); g_kh[base + lane]      = h; g_kl[base + lane]      = bf1(y0 - bfback(h));
        h = bf1(y1); g_kh[base + lane + 32] = h; g_kl[base + lane + 32] = bf1(y1 - bfback(h));
        h = bf1(y2); g_kh[base + lane + 64] = h; g_kl[base + lane + 64] = bf1(y2 - bfback(h));
    }
    {
        float su = c0 + c1 + c2, sq = c0 * c0 + c1 * c1 + c2 * c2;
        #pragma unroll
        for (int o = 16; o; o >>= 1) {
            su += __shfl_xor_sync(0xffffffffu, su, o);
            sq += __shfl_xor_sync(0xffffffffu, sq, o);
        }
        float mean = su * (1.f / 96.f);
        float rs = rsqrtf(sq * (1.f / 96.f) - mean * mean + 1e-5f);
        float y0 = (c0 - mean) * rs * gv[lane]      + bv[lane];
        float y1 = (c1 - mean) * rs * gv[lane + 32] + bv[lane + 32];
        float y2 = (c2 - mean) * rs * gv[lane + 64] + bv[lane + 64];
        u16 h;
        h = bf1(y0); g_vh[base + lane]      = h; g_vl[base + lane]      = bf1(y0 - bfback(h));
        h = bf1(y1); g_vh[base + lane + 32] = h; g_vl[base + lane + 32] = bf1(y1 - bfback(h));
        h = bf1(y2); g_vh[base + lane + 64] = h; g_vl[base + lane + 64] = bf1(y2 - bfback(h));
    }
}

// =====================================================================
// Kernel A: q pools + fused kv pools + weight split (blockIdx ranges)
// Pool weights staged into SMEM once per block (conflict-free LDS:
// lane*9+w mod 32 hits all distinct banks since gcd(9,32)=1).
// =====================================================================
__global__ __launch_bounds__(256)
void pre_kernel(const float* __restrict__ hs,
                const float* __restrict__ pqw, const float* __restrict__ gq, const float* __restrict__ betaq,
                const float* __restrict__ pkw, const float* __restrict__ gk, const float* __restrict__ betak,
                const float* __restrict__ pvw, const float* __restrict__ gv, const float* __restrict__ betav,
                const float* __restrict__ Wq, const float* __restrict__ Wk, const float* __restrict__ Wv)
{
    __shared__ float spw[2 * 96 * 9];   // q: first 864; kv: k then v
    int bid  = blockIdx.x;
    int tid  = threadIdx.x;
    int warp = tid >> 5;
    if (bid < QPB) {
        for (int i = tid; i < 96 * 9; i += 256) spw[i] = pqw[i];
        __syncthreads();
        pool_token_q(hs, spw, gq, betaq, bid * 8 + warp);
    } else if (bid < QPB + KPB) {
        for (int i = tid; i < 96 * 9; i += 256) {
            spw[i]          = pkw[i];
            spw[96 * 9 + i] = pvw[i];
        }
        __syncthreads();
        pool_token_kv(hs, spw, gk, betak, spw + 96 * 9, gv, betav, (bid - QPB) * 8 + warp);
    } else {
        int widx = bid - (QPB + KPB);
        const float* W = (widx == 0) ? Wq : (widx == 1) ? Wk : Wv;
        u32* outh = g_Wt[widx][0];
        u32* outl = g_Wt[widx][1];
        for (int i = tid; i < 192 * 48; i += 256) {
            int n = i / 48, w = i - n * 48;
            float f0 = W[(2 * w)     * 192 + n];
            float f1 = W[(2 * w + 1) * 192 + n];
            u16 h0 = bf1(f0); u16 l0 = bf1(f0 - bfback(h0));
            u16 h1 = bf1(f1); u16 l1 = bf1(f1 - bfback(h1));
            int pos = n * 48 + (w & 3) * 12 + (w >> 2);
            outh[pos] = (u32)h0 | ((u32)h1 << 16);
            outl[pos] = (u32)l0 | ((u32)l1 << 16);
        }
    }
}

// =====================================================================
// Kernel B: fused q/k/v projection via bf16-split tensor cores
// =====================================================================
#define QJB 393   // (MQ+127)/128
#define KJB 99    // (MK+127)/128
#define PROJ_SMEM (2 * 192 * 48 * 4)   // 73728
__global__ __launch_bounds__(256, 2)
void proj_mma_kernel(const float* __restrict__ bq,
                     const float* __restrict__ bk,
                     const float* __restrict__ bv)
{
    int bid = blockIdx.x;
    int widx, rb, M;
    const u16 *xh, *xl;
    const float* bias;
    float* Y;
    if (bid < QJB)            { widx = 0; rb = bid;             xh = g_qh; xl = g_ql; bias = bq; Y = g_qp; M = MQ; }
    else if (bid < QJB + KJB) { widx = 1; rb = bid - QJB;       xh = g_kh; xl = g_kl; bias = bk; Y = g_kp; M = MK; }
    else                      { widx = 2; rb = bid - QJB - KJB; xh = g_vh; xl = g_vl; bias = bv; Y = g_vp; M = MK; }

    extern __shared__ u32 swp[];
    u32* sWh = swp;
    u32* sWl = swp + 192 * 48;
    {
        const uint4* srcH = (const uint4*)g_Wt[widx][0];
        const uint4* srcL = (const uint4*)g_Wt[widx][1];
        uint4* dH = (uint4*)sWh;
        uint4* dL = (uint4*)sWl;
        for (int i = threadIdx.x; i < 192 * 48 / 4; i += 256) {
            dH[i] = srcH[i]; dL[i] = srcL[i];
        }
    }
    __syncthreads();

    int warp = threadIdx.x >> 5, lane = threadIdx.x & 31;
    int g = lane >> 2, t = lane & 3;
    int r0 = rb * 128 + warp * 16 + g;
    int r1 = r0 + 8;
    int r0c = (r0 < M) ? r0 : M - 1;
    int r1c = (r1 < M) ? r1 : M - 1;

    const u32* x0h = (const u32*)(xh + (size_t)r0c * CIN);
    const u32* x1h = (const u32*)(xh + (size_t)r1c * CIN);
    const u32* x0l = (const u32*)(xl + (size_t)r0c * CIN);
    const u32* x1l = (const u32*)(xl + (size_t)r1c * CIN);

    u32 ah[6][4], al[6][4];
    #pragma unroll
    for (int ks = 0; ks < 6; ks++) {
        ah[ks][0] = x0h[8 * ks + t];     ah[ks][1] = x1h[8 * ks + t];
        ah[ks][2] = x0h[8 * ks + t + 4]; ah[ks][3] = x1h[8 * ks + t + 4];
        al[ks][0] = x0l[8 * ks + t];     al[ks][1] = x1l[8 * ks + t];
        al[ks][2] = x0l[8 * ks + t + 4]; al[ks][3] = x1l[8 * ks + t + 4];
    }

    #pragma unroll 2
    for (int nt = 0; nt < 24; nt++) {
        const uint4* hp = (const uint4*)(sWh + (8 * nt + g) * 48) + t * 3;
        const uint4* lp = (const uint4*)(sWl + (8 * nt + g) * 48) + t * 3;
        uint4 H0 = hp[0], H1 = hp[1], H2 = hp[2];
        uint4 L0 = lp[0], L1 = lp[1], L2 = lp[2];
        float aA[4] = {0.f, 0.f, 0.f, 0.f};
        float aB[4] = {0.f, 0.f, 0.f, 0.f};
        mma_bf16(aA, ah[0], H0.x, H0.y); mma_bf16(aB, al[0], H0.x, H0.y);
        mma_bf16(aA, ah[1], H0.z, H0.w); mma_bf16(aB, al[1], H0.z, H0.w);
        mma_bf16(aA, ah[2], H1.x, H1.y); mma_bf16(aB, al[2], H1.x, H1.y);
        mma_bf16(aA, ah[3], H1.z, H1.w); mma_bf16(aB, al[3], H1.z, H1.w);
        mma_bf16(aA, ah[4], H2.x, H2.y); mma_bf16(aB, al[4], H2.x, H2.y);
        mma_bf16(aA, ah[5], H2.z, H2.w); mma_bf16(aB, al[5], H2.z, H2.w);
        mma_bf16(aB, ah[0], L0.x, L0.y);
        mma_bf16(aB, ah[1], L0.z, L0.w);
        mma_bf16(aB, ah[2], L1.x, L1.y);
        mma_bf16(aB, ah[3], L1.z, L1.w);
        mma_bf16(aB, ah[4], L2.x, L2.y);
        mma_bf16(aB, ah[5], L2.z, L2.w);

        float2 bvv = *(const float2*)(bias + 8 * nt + 2 * t);
        if (r0 < M)
            *(float2*)(Y + (size_t)r0 * COUT + 8 * nt + 2 * t) =
                make_float2(aA[0] + aB[0] + bvv.x, aA[1] + aB[1] + bvv.y);
        if (r1 < M)
            *(float2*)(Y + (size_t)r1 * COUT + 8 * nt + 2 * t) =
                make_float2(aA[2] + aB[2] + bvv.x, aA[3] + aB[3] + bvv.y);
    }
}

// =====================================================================
// Kernel C: rel-pos bias via tensor cores (round-11 version).
// =====================================================================
#define RELN_SMEM (112 * 48 * 4 + 8 * 16 * 112 * 4)   // 78848
__global__ __launch_bounds__(256, 2)
void rel_mma_kernel(const float* __restrict__ relh,
                    const float* __restrict__ relw)
{
    extern __shared__ u32 shm[];
    u32*   sRt = shm;                        // [112][48]
    float* sE  = (float*)(shm + 112 * 48);   // per-warp [16][112]

    int bid  = blockIdx.x;
    int bh   = bid >> 1, half = bid & 1;
    int b    = bh >> 1, head = bh & 1;
    int tid  = threadIdx.x;
    int warp = tid >> 5, lane = tid & 31;
    int g = lane >> 2, t = lane & 3;

    for (int i = tid; i < 112 * 48; i += 256) {
        int n = i / 48, w = i - n * 48;
        float r0 = 0.f, r1 = 0.f;
        if (n < 55)       { r0 = relh[n * 96 + 2 * w];        r1 = relh[n * 96 + 2 * w + 1]; }
        else if (n < 110) { r0 = relw[(n - 55) * 96 + 2 * w]; r1 = relw[(n - 55) * 96 + 2 * w + 1]; }
        sRt[n * 48 + (w & 3) * 12 + (w >> 2)] = bf2(r0 * LOG2E, r1 * LOG2E);
    }
    __syncthreads();

    const float* qbase = g_qp + (size_t)b * NQ * COUT + head * HDIM;
    float* myE = sE + warp * (16 * 112);
    int mEnd = (half == 0) ? 25 : 49;

    for (int m = half * 25 + warp; m < mEnd; m += 8) {
        int s0 = m * 16 + g;
        const float* q0 = qbase + (size_t)(s0 + 1) * COUT;
        const float* q1 = qbase + (size_t)(s0 + 9) * COUT;

        u32 a[6][4];
        #pragma unroll
        for (int ks = 0; ks < 6; ks++) {
            float2 x0 = *(const float2*)(q0 + 16 * ks + 2 * t);
            float2 x1 = *(const float2*)(q1 + 16 * ks + 2 * t);
            float2 x2 = *(const float2*)(q0 + 16 * ks + 2 * t + 8);
            float2 x3 = *(const float2*)(q1 + 16 * ks + 2 * t + 8);
            a[ks][0] = bf2(x0.x, x0.y);
            a[ks][1] = bf2(x1.x, x1.y);
            a[ks][2] = bf2(x2.x, x2.y);
            a[ks][3] = bf2(x3.x, x3.y);
        }

        #pragma unroll
        for (int nt = 0; nt < 14; nt++) {
            const uint4* rp = (const uint4*)(sRt + (8 * nt + g) * 48) + t * 3;
            uint4 R0 = rp[0], R1 = rp[1], R2 = rp[2];
            float acc[4] = {0.f, 0.f, 0.f, 0.f};
            mma_bf16(acc, a[0], R0.x, R0.y); mma_bf16(acc, a[1], R0.z, R0.w);
            mma_bf16(acc, a[2], R1.x, R1.y); mma_bf16(acc, a[3], R1.z, R1.w);
            mma_bf16(acc, a[4], R2.x, R2.y); mma_bf16(acc, a[5], R2.z, R2.w);
            *(float2*)(myE + g * 112 + 8 * nt + 2 * t)       = make_float2(acc[0], acc[1]);
            *(float2*)(myE + (g + 8) * 112 + 8 * nt + 2 * t) = make_float2(acc[2], acc[3]);
        }
        __syncwarp();

        int sbase = m * 16;
        float* outp = g_ehw + ((size_t)bh * 784 + sbase) * 28;
        #pragma unroll
        for (int it = 0; it < 14; it++) {
            int idx = lane + 32 * it;
            int r = idx / 28, k = idx - r * 28;
            int s = sbase + r;
            int qy = s / 28, qx = s - qy * 28;
            int col = (k < 14) ? (qy - 2 * k + 26) : (55 + qx - 2 * (k - 14) + 26);
            outp[idx] = myE[r * 112 + col];
        }
        __syncwarp();
    }
}

// =====================================================================
// Kernel D: fused attention — round-11 version (grid 128, 512 threads,
// 16 warps, 1 CTA/SM, inline staging once per bh, chunk-4 tile body).
// =====================================================================
#define SK_OFF   0
#define SVT_OFF  54400
#define ATTN_SMEM 98944

__global__ __launch_bounds__(512, 1)
void attn_kernel(float* __restrict__ out)
{
    extern __shared__ char smem[];
    u32* sK32 = (u32*)(smem + SK_OFF);
    u32* sV32 = (u32*)(smem + SVT_OFF);
    int bh   = blockIdx.x;
    int b    = bh >> 1, head = bh & 1;
    int tid  = threadIdx.x;
    int warp = tid >> 5, lane = tid & 31;
    int g = lane >> 2, t = lane & 3;

    const float SC2 = SCALE * LOG2E;

    // ---- staging (once per bh, spread over 512 threads) ----
    for (int i = tid; i < 200 * 64; i += 512) {
        int j = i >> 6, c2 = i & 63;
        u32 val = 0;
        if (j < NK) {
            if (c2 < 48) {
                const float* kp = g_kp + ((size_t)b * NK + j) * COUT + head * HDIM + 2 * c2;
                val = bf2(SC2 * kp[0], SC2 * kp[1]);
            } else if (j >= 1) {
                int ky = (j - 1) / 14, kx = (j - 1) - 14 * ky;
                int i0 = 2 * (c2 - 48);
                int i1 = i0 + 1;
                bool lo = (i0 < 14) ? (i0 == ky) : ((i0 < 28) && (i0 - 14 == kx));
                bool hi = (i1 < 14) ? (i1 == ky) : ((i1 < 28) && (i1 - 14 == kx));
                val = (lo ? 0x3F80u : 0u) | (hi ? 0x3F800000u : 0u);
            }
        }
        sK32[j * 68 + (c2 & 3) * 16 + (c2 >> 2)] = val;
    }
    for (int i = tid; i < 108 * 96; i += 512) {
        int w = i / 96, c = i - w * 96;
        int j0 = 2 * w;
        const float* vp = g_vp + ((size_t)b * NK + j0) * COUT + head * HDIM + c;
        float v0 = (j0     < NK) ? vp[0]    : 0.f;
        float v1 = (j0 + 1 < NK) ? vp[COUT] : 0.f;
        sV32[c * 116 + (w & 3) * 28 + (w >> 2)] = bf2(v0, v1);
    }
    __syncthreads();

    const float* qbase = g_qp + (size_t)b * NQ * COUT + head * HDIM;
    const float* ebase = g_ehw + (size_t)bh * 784 * 28;

    for (int tile = warp; tile < 50; tile += 16) {
        int q0 = tile * 16;
        int r0 = q0 + g, r1 = r0 + 8;
        int r0c = (r0 < NQ) ? r0 : NQ - 1;
        int r1c = (r1 < NQ) ? r1 : NQ - 1;

        const float* q_r0 = qbase + (size_t)r0c * COUT;
        const float* q_r1 = qbase + (size_t)r1c * COUT;
        u32 a[8][4];
        #pragma unroll
        for (int ks = 0; ks < 6; ks++) {
            float2 x0 = *(const float2*)(q_r0 + 16 * ks + 2 * t);
            float2 x1 = *(const float2*)(q_r1 + 16 * ks + 2 * t);
            float2 x2 = *(const float2*)(q_r0 + 16 * ks + 2 * t + 8);
            float2 x3 = *(const float2*)(q_r1 + 16 * ks + 2 * t + 8);
            a[ks][0] = bf2(x0.x, x0.y);
            a[ks][1] = bf2(x1.x, x1.y);
            a[ks][2] = bf2(x2.x, x2.y);
            a[ks][3] = bf2(x3.x, x3.y);
        }
        {
            bool v0ok = (r0 >= 1 && r0 < NQ);
            bool v1ok = (r1 >= 1 && r1 < NQ);
            const float* e0p = ebase + (size_t)(v0ok ? r0 - 1 : 0) * 28;
            const float* e1p = ebase + (size_t)(v1ok ? r1 - 1 : 0) * 28;
            float2 h;
            h = *(const float2*)(e0p + 2 * t);       a[6][0] = v0ok ? bf2(h.x, h.y) : 0u;
            h = *(const float2*)(e1p + 2 * t);       a[6][1] = v1ok ? bf2(h.x, h.y) : 0u;
            h = *(const float2*)(e0p + 8 + 2 * t);   a[6][2] = v0ok ? bf2(h.x, h.y) : 0u;
            h = *(const float2*)(e1p + 8 + 2 * t);   a[6][3] = v1ok ? bf2(h.x, h.y) : 0u;
            h = *(const float2*)(e0p + 16 + 2 * t);  a[7][0] = v0ok ? bf2(h.x, h.y) : 0u;
            h = *(const float2*)(e1p + 16 + 2 * t);  a[7][1] = v1ok ? bf2(h.x, h.y) : 0u;
            if (t < 2) {
                h = *(const float2*)(e0p + 24 + 2 * t); a[7][2] = v0ok ? bf2(h.x, h.y) : 0u;
                h = *(const float2*)(e1p + 24 + 2 * t); a[7][3] = v1ok ? bf2(h.x, h.y) : 0u;
            } else { a[7][2] = 0u; a[7][3] = 0u; }
        }

        float o[12][4];
        #pragma unroll
        for (int nt = 0; nt < 12; nt++)
            #pragma unroll
            for (int i = 0; i < 4; i++) o[nt][i] = 0.f;
        float slo = 0.f, shi = 0.f;

        #pragma unroll
        for (int ch = 0; ch < 6; ch++) {
            float acc[4][4];
            #pragma unroll
            for (int nt = 0; nt < 4; nt++)
                #pragma unroll
                for (int i = 0; i < 4; i++) acc[nt][i] = 0.f;

            #pragma unroll
            for (int nt2 = 0; nt2 < 4; nt2++) {
                int nt = 4 * ch + nt2;
                const uint4* kp = (const uint4*)(sK32 + (8 * nt + g) * 68 + t * 16);
                uint4 K0 = kp[0], K1 = kp[1], K2 = kp[2], K3 = kp[3];
                float* d = acc[nt2];
                mma_bf16(d, a[0], K0.x, K0.y); mma_bf16(d, a[1], K0.z, K0.w);
                mma_bf16(d, a[2], K1.x, K1.y); mma_bf16(d, a[3], K1.z, K1.w);
                mma_bf16(d, a[4], K2.x, K2.y); mma_bf16(d, a[5], K2.z, K2.w);
                mma_bf16(d, a[6], K3.x, K3.y); mma_bf16(d, a[7], K3.z, K3.w);
            }

            u32 pa[2][4];
            #pragma unroll
            for (int ks2 = 0; ks2 < 2; ks2++) {
                float e00 = ex2(acc[2 * ks2][0]),     e01 = ex2(acc[2 * ks2][1]);
                float e02 = ex2(acc[2 * ks2][2]),     e03 = ex2(acc[2 * ks2][3]);
                float e10 = ex2(acc[2 * ks2 + 1][0]), e11 = ex2(acc[2 * ks2 + 1][1]);
                float e12 = ex2(acc[2 * ks2 + 1][2]), e13 = ex2(acc[2 * ks2 + 1][3]);
                slo += e00 + e01 + e10 + e11;
                shi += e02 + e03 + e12 + e13;
                pa[ks2][0] = bf2(e00, e01); pa[ks2][1] = bf2(e02, e03);
                pa[ks2][2] = bf2(e10, e11); pa[ks2][3] = bf2(e12, e13);
            }

            #pragma unroll
            for (int nt = 0; nt < 12; nt++) {
                const uint4* vp = (const uint4*)(sV32 + (8 * nt + g) * 116 + t * 28 + ch * 4);
                uint4 V = vp[0];
                float* d = o[nt];
                mma_bf16(d, pa[0], V.x, V.y);
                mma_bf16(d, pa[1], V.z, V.w);
            }
        }

        // ---- tail n-tile 24 (j = 192..196) ----
        {
            float at[4] = {0.f, 0.f, 0.f, 0.f};
            const uint4* kp = (const uint4*)(sK32 + (192 + g) * 68 + t * 16);
            uint4 K0 = kp[0], K1 = kp[1], K2 = kp[2], K3 = kp[3];
            mma_bf16(at, a[0], K0.x, K0.y); mma_bf16(at, a[1], K0.z, K0.w);
            mma_bf16(at, a[2], K1.x, K1.y); mma_bf16(at, a[3], K1.z, K1.w);
            mma_bf16(at, a[4], K2.x, K2.y); mma_bf16(at, a[5], K2.z, K2.w);
            mma_bf16(at, a[6], K3.x, K3.y); mma_bf16(at, a[7], K3.z, K3.w);
            int j0 = 192 + 2 * t;
            float e0 = (j0     < NK) ? ex2(at[0]) : 0.f;
            float e1 = (j0 + 1 < NK) ? ex2(at[1]) : 0.f;
            float e2 = (j0     < NK) ? ex2(at[2]) : 0.f;
            float e3 = (j0 + 1 < NK) ? ex2(at[3]) : 0.f;
            slo += e0 + e1; shi += e2 + e3;
            u32 paT[4] = { bf2(e0, e1), bf2(e2, e3), 0u, 0u };
            #pragma unroll
            for (int nt = 0; nt < 12; nt++) {
                uint4 V = *(const uint4*)(sV32 + (8 * nt + g) * 116 + t * 28 + 24);
                mma_bf16(o[nt], paT, V.x, V.y);
            }
        }

        slo += __shfl_xor_sync(0xffffffffu, slo, 1);
        slo += __shfl_xor_sync(0xffffffffu, slo, 2);
        shi += __shfl_xor_sync(0xffffffffu, shi, 1);
        shi += __shfl_xor_sync(0xffffffffu, shi, 2);
        float ilo = 1.f / slo, ihi = 1.f / shi;

        float* obase = out + (size_t)b * NQ * COUT + head * HDIM;
        #pragma unroll
        for (int nt = 0; nt < 12; nt++) {
            int c = 8 * nt + 2 * t;
            if (r0 < NQ) {
                float2 r = make_float2(o[nt][0] * ilo, o[nt][1] * ilo);
                if (r0 >= 1) {
                    float2 q = *(const float2*)(qbase + (size_t)r0 * COUT + c);
                    r.x += q.x; r.y += q.y;
                }
                *(float2*)(obase + (size_t)r0 * COUT + c) = r;
            }
            if (r1 < NQ) {
                float2 r = make_float2(o[nt][2] * ihi, o[nt][3] * ihi);
                if (r1 >= 1) {
                    float2 q = *(const float2*)(qbase + (size_t)r1 * COUT + c);
                    r.x += q.x; r.y += q.y;
                }
                *(float2*)(obase + (size_t)r1 * COUT + c) = r;
            }
        }
    }
}

// =====================================================================
// launch: pre -> proj -> rel -> attn
// =====================================================================
extern "C" void kernel_launch(void* const* d_in, const int* in_sizes, int n_in,
                              void* d_out, int out_size)
{
    const float* hs    = (const float*)d_in[0];
    const float* Wq    = (const float*)d_in[1];
    const float* bq    = (const float*)d_in[2];
    const float* Wk    = (const float*)d_in[3];
    const float* bk    = (const float*)d_in[4];
    const float* Wv    = (const float*)d_in[5];
    const float* bv    = (const float*)d_in[6];
    const float* pqw   = (const float*)d_in[7];
    const float* pkw   = (const float*)d_in[8];
    const float* pvw   = (const float*)d_in[9];
    const float* gq    = (const float*)d_in[10];
    const float* betaq = (const float*)d_in[11];
    const float* gk    = (const float*)d_in[12];
    const float* betak = (const float*)d_in[13];
    const float* gv    = (const float*)d_in[14];
    const float* betav = (const float*)d_in[15];
    const float* relh  = (const float*)d_in[16];
    const float* relw  = (const float*)d_in[17];
    float* out = (float*)d_out;

    cudaFuncSetAttribute(proj_mma_kernel, cudaFuncAttributeMaxDynamicSharedMemorySize, PROJ_SMEM);
    cudaFuncSetAttribute(rel_mma_kernel, cudaFuncAttributeMaxDynamicSharedMemorySize, RELN_SMEM);
    cudaFuncSetAttribute(attn_kernel,  cudaFuncAttributeMaxDynamicSharedMemorySize, ATTN_SMEM);

    // A: q pools + fused kv pools + weight split (weights in smem)
    pre_kernel<<<QPB + KPB + 3, 256>>>(hs,
        pqw, gq, betaq, pkw, gk, betak, pvw, gv, betav, Wq, Wk, Wv);

    // B: all three projections
    proj_mma_kernel<<<QJB + 2 * KJB, 256, PROJ_SMEM>>>(bq, bk, bv);

    // C: rel-pos bias via tensor cores
    rel_mma_kernel<<<BATCH * NHEAD * 2, 256, RELN_SMEM>>>(relh, relw);

    // D: fused tensor-core attention (round-11 config)
    attn_kernel<<<BATCH * NHEAD, 512, ATTN_SMEM>>>(out);
}

// round 16
// speedup vs baseline: 1.1199x; 1.0187x over previous
#include <cuda_runtime.h>
#include <cuda_bf16.h>
#include <math.h>

// ---------------- static problem constants ----------------
#define BATCH   64
#define NTOT    3137          // 56*56+1
#define CIN     96
#define COUT    192
#define NHEAD   2
#define HDIM    96
#define HFS     56
#define QH      28
#define KH      14
#define NQ      785           // 28*28+1
#define NK      197           // 14*14+1
#define MQ      (BATCH * NQ)  // 50240
#define MK      (BATCH * NK)  // 12608
#define SCALE   0.10206207261596577f   // 96^-0.5
#define LOG2E   1.4426950408889634f

#define QPB     (MQ / 8)      // 6280 q-pool blocks
#define KPB     (MK / 8)      // 1576 fused kv-pool blocks

typedef unsigned long long u64;
typedef unsigned int u32;
typedef unsigned short u16;

__device__ __forceinline__ u32 bf2(float lo, float hi) {
    u32 r; asm("cvt.rn.bf16x2.f32 %0, %1, %2;" : "=r"(r) : "f"(hi), "f"(lo)); return r;
}
__device__ __forceinline__ u16 bf1(float v) {
    u16 r; asm("cvt.rn.bf16.f32 %0, %1;" : "=h"(r) : "f"(v)); return r;
}
__device__ __forceinline__ float bfback(u16 h) {
    return __uint_as_float(((u32)h) << 16);
}
__device__ __forceinline__ float ex2(float x) {
    float y; asm("ex2.approx.f32 %0, %1;" : "=f"(y) : "f"(x)); return y;
}
__device__ __forceinline__ void mma_bf16(float* d, const u32* a, u32 b0, u32 b1) {
    asm volatile("mma.sync.aligned.m16n8k16.row.col.f32.bf16.bf16.f32 "
        "{%0,%1,%2,%3},{%4,%5,%6,%7},{%8,%9},{%0,%1,%2,%3};"
        : "+f"(d[0]), "+f"(d[1]), "+f"(d[2]), "+f"(d[3])
        : "r"(a[0]), "r"(a[1]), "r"(a[2]), "r"(a[3]), "r"(b0), "r"(b1));
}

// ---------------- scratch (device globals) ----------------
__device__ u16  g_qh[MQ * CIN];
__device__ u16  g_ql[MQ * CIN];
__device__ u16  g_kh[MK * CIN];
__device__ u16  g_kl[MK * CIN];
__device__ u16  g_vh[MK * CIN];
__device__ u16  g_vl[MK * CIN];
__device__ float g_qp[MQ * COUT];
__device__ float g_kp[MK * COUT];
__device__ float g_vp[MK * COUT];
__device__ float g_ehw[BATCH * NHEAD * 784 * 28];   // eh[14]|ew[14], pre-scaled by log2e
// W split: [weight][term hi/lo][192 rows(n) x 48 u32 (k-pairs), LDS.128-permuted]
__device__ __align__(16) u32 g_Wt[3][2][192 * 48];

// =====================================================================
// q pool: one token per warp + LN + bf16 hi/lo split stores
// (pw points to SHARED memory; interior tokens take the unchecked path)
// =====================================================================
__device__ __forceinline__ void pool_token_q(
    const float* __restrict__ hs, const float* pw,
    const float* __restrict__ gam, const float* __restrict__ bet,
    int tok)
{
    int lane = threadIdx.x & 31;
    int b = tok / NQ;
    int t = tok - b * NQ;

    float v0 = 0.f, v1 = 0.f, v2 = 0.f;
    if (t == 0) {
        const float* p = hs + (size_t)b * NTOT * CIN;
        v0 = p[lane]; v1 = p[lane + 32]; v2 = p[lane + 64];
    } else {
        int s   = t - 1;
        int y   = s / QH, x = s - y * QH;
        int iy0 = y * 2 - 1, ix0 = x * 2 - 1;
        if (y > 0 && y < QH - 1 && x > 0 && x < QH - 1) {
            const float* base = hs + ((size_t)b * NTOT + 1 + iy0 * HFS + ix0) * CIN;
            #pragma unroll
            for (int dy = 0; dy < 3; dy++) {
                #pragma unroll
                for (int dx = 0; dx < 3; dx++) {
                    const float* p = base + (dy * HFS + dx) * CIN;
                    int w = dy * 3 + dx;
                    v0 += pw[(lane)      * 9 + w] * p[lane];
                    v1 += pw[(lane + 32) * 9 + w] * p[lane + 32];
                    v2 += pw[(lane + 64) * 9 + w] * p[lane + 64];
                }
            }
        } else {
            #pragma unroll
            for (int dy = 0; dy < 3; dy++) {
                int iy = iy0 + dy;
                if (iy < 0 || iy >= HFS) continue;
                #pragma unroll
                for (int dx = 0; dx < 3; dx++) {
                    int ix = ix0 + dx;
                    if (ix < 0 || ix >= HFS) continue;
                    const float* p = hs + ((size_t)b * NTOT + 1 + iy * HFS + ix) * CIN;
                    int w = dy * 3 + dx;
                    v0 += pw[(lane)      * 9 + w] * p[lane];
                    v1 += pw[(lane + 32) * 9 + w] * p[lane + 32];
                    v2 += pw[(lane + 64) * 9 + w] * p[lane + 64];
                }
            }
        }
    }
    float su  = v0 + v1 + v2;
    float sq  = v0 * v0 + v1 * v1 + v2 * v2;
    #pragma unroll
    for (int o = 16; o; o >>= 1) {
        su += __shfl_xor_sync(0xffffffffu, su, o);
        sq += __shfl_xor_sync(0xffffffffu, sq, o);
    }
    float mean = su * (1.f / 96.f);
    float rs   = rsqrtf(sq * (1.f / 96.f) - mean * mean + 1e-5f);
    float y0 = (v0 - mean) * rs * gam[lane]      + bet[lane];
    float y1 = (v1 - mean) * rs * gam[lane + 32] + bet[lane + 32];
    float y2 = (v2 - mean) * rs * gam[lane + 64] + bet[lane + 64];
    size_t base = (size_t)tok * CIN;
    u16 h;
    h = bf1(y0); g_qh[base + lane]      = h; g_ql[base + lane]      = bf1(y0 - bfback(h));
    h = bf1(y1); g_qh[base + lane + 32] = h; g_ql[base + lane + 32] = bf1(y1 - bfback(h));
    h = bf1(y2); g_qh[base + lane + 64] = h; g_ql[base + lane + 64] = bf1(y2 - bfback(h));
}

// =====================================================================
// fused k+v pool: one token per warp, shared input loads, two LNs
// =====================================================================
__device__ __forceinline__ void pool_token_kv(
    const float* __restrict__ hs,
    const float* pwk, const float* __restrict__ gk, const float* __restrict__ bk,
    const float* pwv, const float* __restrict__ gv, const float* __restrict__ bv,
    int tok)
{
    int lane = threadIdx.x & 31;
    int b = tok / NK;
    int t = tok - b * NK;

    float a0 = 0.f, a1 = 0.f, a2 = 0.f;   // k
    float c0 = 0.f, c1 = 0.f, c2 = 0.f;   // v
    if (t == 0) {
        const float* p = hs + (size_t)b * NTOT * CIN;
        a0 = c0 = p[lane]; a1 = c1 = p[lane + 32]; a2 = c2 = p[lane + 64];
    } else {
        int s   = t - 1;
        int y   = s / KH, x = s - y * KH;
        int iy0 = y * 4 - 1, ix0 = x * 4 - 1;
        if (y > 0 && y < KH - 1 && x > 0 && x < KH - 1) {
            const float* base = hs + ((size_t)b * NTOT + 1 + iy0 * HFS + ix0) * CIN;
            #pragma unroll
            for (int dy = 0; dy < 3; dy++) {
                #pragma unroll
                for (int dx = 0; dx < 3; dx++) {
                    const float* p = base + (dy * HFS + dx) * CIN;
                    int w = dy * 3 + dx;
                    float p0 = p[lane], p1 = p[lane + 32], p2 = p[lane + 64];
                    a0 += pwk[(lane)      * 9 + w] * p0;
                    a1 += pwk[(lane + 32) * 9 + w] * p1;
                    a2 += pwk[(lane + 64) * 9 + w] * p2;
                    c0 += pwv[(lane)      * 9 + w] * p0;
                    c1 += pwv[(lane + 32) * 9 + w] * p1;
                    c2 += pwv[(lane + 64) * 9 + w] * p2;
                }
            }
        } else {
            #pragma unroll
            for (int dy = 0; dy < 3; dy++) {
                int iy = iy0 + dy;
                if (iy < 0 || iy >= HFS) continue;
                #pragma unroll
                for (int dx = 0; dx < 3; dx++) {
                    int ix = ix0 + dx;
                    if (ix < 0 || ix >= HFS) continue;
                    const float* p = hs + ((size_t)b * NTOT + 1 + iy * HFS + ix) * CIN;
                    int w = dy * 3 + dx;
                    float p0 = p[lane], p1 = p[lane + 32], p2 = p[lane + 64];
                    a0 += pwk[(lane)      * 9 + w] * p0;
                    a1 += pwk[(lane + 32) * 9 + w] * p1;
                    a2 += pwk[(lane + 64) * 9 + w] * p2;
                    c0 += pwv[(lane)      * 9 + w] * p0;
                    c1 += pwv[(lane + 32) * 9 + w] * p1;
                    c2 += pwv[(lane + 64) * 9 + w] * p2;
                }
            }
        }
    }
    size_t base = (size_t)tok * CIN;
    {
        float su = a0 + a1 + a2, sq = a0 * a0 + a1 * a1 + a2 * a2;
        #pragma unroll
        for (int o = 16; o; o >>= 1) {
            su += __shfl_xor_sync(0xffffffffu, su, o);
            sq += __shfl_xor_sync(0xffffffffu, sq, o);
        }
        float mean = su * (1.f / 96.f);
        float rs = rsqrtf(sq * (1.f / 96.f) - mean * mean + 1e-5f);
        float y0 = (a0 - mean) * rs * gk[lane]      + bk[lane];
        float y1 = (a1 - mean) * rs * gk[lane + 32] + bk[lane + 32];
        float y2 = (a2 - mean) * rs * gk[lane + 64] + bk[lane + 64];
        u16 h;
        h = bf1(y0); g_kh[base + lane]      = h; g_kl[base + lane]      = bf1(y0 - bfback(h));
        h = bf1(y1); g_kh[base + lane + 32] = h; g_kl[base + lane + 32] = bf1(y1 - bfback(h));
        h = bf1(y2); g_kh[base + lane + 64] = h; g_kl[base + lane + 64] = bf1(y2 - bfback(h));
    }
    {
        float su = c0 + c1 + c2, sq = c0 * c0 + c1 * c1 + c2 * c2;
        #pragma unroll
        for (int o = 16; o; o >>= 1) {
            su += __shfl_xor_sync(0xffffffffu, su, o);
            sq += __shfl_xor_sync(0xffffffffu, sq, o);
        }
        float mean = su * (1.f / 96.f);
        float rs = rsqrtf(sq * (1.f / 96.f) - mean * mean + 1e-5f);
        float y0 = (c0 - mean) * rs * gv[lane]      + bv[lane];
        float y1 = (c1 - mean) * rs * gv[lane + 32] + bv[lane + 32];
        float y2 = (c2 - mean) * rs * gv[lane + 64] + bv[lane + 64];
        u16 h;
        h = bf1(y0); g_vh[base + lane]      = h; g_vl[base + lane]      = bf1(y0 - bfback(h));
        h = bf1(y1); g_vh[base + lane + 32] = h; g_vl[base + lane + 32] = bf1(y1 - bfback(h));
        h = bf1(y2); g_vh[base + lane + 64] = h; g_vl[base + lane + 64] = bf1(y2 - bfback(h));
    }
}

// =====================================================================
// Kernel A: q pools + fused kv pools + weight split (blockIdx ranges)
// =====================================================================
__global__ __launch_bounds__(256)
void pre_kernel(const float* __restrict__ hs,
                const float* __restrict__ pqw, const float* __restrict__ gq, const float* __restrict__ betaq,
                const float* __restrict__ pkw, const float* __restrict__ gk, const float* __restrict__ betak,
                const float* __restrict__ pvw, const float* __restrict__ gv, const float* __restrict__ betav,
                const float* __restrict__ Wq, const float* __restrict__ Wk, const float* __restrict__ Wv)
{
    __shared__ float spw[2 * 96 * 9];
    int bid  = blockIdx.x;
    int tid  = threadIdx.x;
    int warp = tid >> 5;
    if (bid < QPB) {
        for (int i = tid; i < 96 * 9; i += 256) spw[i] = pqw[i];
        __syncthreads();
        pool_token_q(hs, spw, gq, betaq, bid * 8 + warp);
    } else if (bid < QPB + KPB) {
        for (int i = tid; i < 96 * 9; i += 256) {
            spw[i]          = pkw[i];
            spw[96 * 9 + i] = pvw[i];
        }
        __syncthreads();
        pool_token_kv(hs, spw, gk, betak, spw + 96 * 9, gv, betav, (bid - QPB) * 8 + warp);
    } else {
        int widx = bid - (QPB + KPB);
        const float* W = (widx == 0) ? Wq : (widx == 1) ? Wk : Wv;
        u32* outh = g_Wt[widx][0];
        u32* outl = g_Wt[widx][1];
        for (int i = tid; i < 192 * 48; i += 256) {
            int n = i / 48, w = i - n * 48;
            float f0 = W[(2 * w)     * 192 + n];
            float f1 = W[(2 * w + 1) * 192 + n];
            u16 h0 = bf1(f0); u16 l0 = bf1(f0 - bfback(h0));
            u16 h1 = bf1(f1); u16 l1 = bf1(f1 - bfback(h1));
            int pos = n * 48 + (w & 3) * 12 + (w >> 2);
            outh[pos] = (u32)h0 | ((u32)h1 << 16);
            outl[pos] = (u32)l0 | ((u32)l1 << 16);
        }
    }
}

// =====================================================================
// Kernel B: fused q/k/v projection via bf16-split tensor cores.
// 256 rows per block (two 128-row halves reusing staged weights).
// =====================================================================
#define QJB 197   // ceil(MQ/256)
#define KJB 50    // ceil(MK/256)
#define PROJ_SMEM (2 * 192 * 48 * 4)   // 73728
__global__ __launch_bounds__(256, 2)
void proj_mma_kernel(const float* __restrict__ bq,
                     const float* __restrict__ bk,
                     const float* __restrict__ bv)
{
    int bid = blockIdx.x;
    int widx, rb, M;
    const u16 *xh, *xl;
    const float* bias;
    float* Y;
    if (bid < QJB)            { widx = 0; rb = bid;             xh = g_qh; xl = g_ql; bias = bq; Y = g_qp; M = MQ; }
    else if (bid < QJB + KJB) { widx = 1; rb = bid - QJB;       xh = g_kh; xl = g_kl; bias = bk; Y = g_kp; M = MK; }
    else                      { widx = 2; rb = bid - QJB - KJB; xh = g_vh; xl = g_vl; bias = bv; Y = g_vp; M = MK; }

    extern __shared__ u32 swp[];
    u32* sWh = swp;
    u32* sWl = swp + 192 * 48;
    {
        const uint4* srcH = (const uint4*)g_Wt[widx][0];
        const uint4* srcL = (const uint4*)g_Wt[widx][1];
        uint4* dH = (uint4*)sWh;
        uint4* dL = (uint4*)sWl;
        for (int i = threadIdx.x; i < 192 * 48 / 4; i += 256) {
            dH[i] = srcH[i]; dL[i] = srcL[i];
        }
    }
    __syncthreads();

    int warp = threadIdx.x >> 5, lane = threadIdx.x & 31;
    int g = lane >> 2, t = lane & 3;

    #pragma unroll
    for (int half = 0; half < 2; half++) {
        int r0 = rb * 256 + half * 128 + warp * 16 + g;
        int r1 = r0 + 8;
        int r0c = (r0 < M) ? r0 : M - 1;
        int r1c = (r1 < M) ? r1 : M - 1;

        const u32* x0h = (const u32*)(xh + (size_t)r0c * CIN);
        const u32* x1h = (const u32*)(xh + (size_t)r1c * CIN);
        const u32* x0l = (const u32*)(xl + (size_t)r0c * CIN);
        const u32* x1l = (const u32*)(xl + (size_t)r1c * CIN);

        u32 ah[6][4], al[6][4];
        #pragma unroll
        for (int ks = 0; ks < 6; ks++) {
            ah[ks][0] = x0h[8 * ks + t];     ah[ks][1] = x1h[8 * ks + t];
            ah[ks][2] = x0h[8 * ks + t + 4]; ah[ks][3] = x1h[8 * ks + t + 4];
            al[ks][0] = x0l[8 * ks + t];     al[ks][1] = x1l[8 * ks + t];
            al[ks][2] = x0l[8 * ks + t + 4]; al[ks][3] = x1l[8 * ks + t + 4];
        }

        #pragma unroll 2
        for (int nt = 0; nt < 24; nt++) {
            const uint4* hp = (const uint4*)(sWh + (8 * nt + g) * 48) + t * 3;
            const uint4* lp = (const uint4*)(sWl + (8 * nt + g) * 48) + t * 3;
            uint4 H0 = hp[0], H1 = hp[1], H2 = hp[2];
            uint4 L0 = lp[0], L1 = lp[1], L2 = lp[2];
            float aA[4] = {0.f, 0.f, 0.f, 0.f};
            float aB[4] = {0.f, 0.f, 0.f, 0.f};
            mma_bf16(aA, ah[0], H0.x, H0.y); mma_bf16(aB, al[0], H0.x, H0.y);
            mma_bf16(aA, ah[1], H0.z, H0.w); mma_bf16(aB, al[1], H0.z, H0.w);
            mma_bf16(aA, ah[2], H1.x, H1.y); mma_bf16(aB, al[2], H1.x, H1.y);
            mma_bf16(aA, ah[3], H1.z, H1.w); mma_bf16(aB, al[3], H1.z, H1.w);
            mma_bf16(aA, ah[4], H2.x, H2.y); mma_bf16(aB, al[4], H2.x, H2.y);
            mma_bf16(aA, ah[5], H2.z, H2.w); mma_bf16(aB, al[5], H2.z, H2.w);
            mma_bf16(aB, ah[0], L0.x, L0.y);
            mma_bf16(aB, ah[1], L0.z, L0.w);
            mma_bf16(aB, ah[2], L1.x, L1.y);
            mma_bf16(aB, ah[3], L1.z, L1.w);
            mma_bf16(aB, ah[4], L2.x, L2.y);
            mma_bf16(aB, ah[5], L2.z, L2.w);

            float2 bvv = *(const float2*)(bias + 8 * nt + 2 * t);
            if (r0 < M)
                *(float2*)(Y + (size_t)r0 * COUT + 8 * nt + 2 * t) =
                    make_float2(aA[0] + aB[0] + bvv.x, aA[1] + aB[1] + bvv.y);
            if (r1 < M)
                *(float2*)(Y + (size_t)r1 * COUT + 8 * nt + 2 * t) =
                    make_float2(aA[2] + aB[2] + bvv.x, aA[3] + aB[3] + bvv.y);
        }
    }
}

// =====================================================================
// Kernel C: rel-pos bias via tensor cores (unchanged).
// =====================================================================
#define RELN_SMEM (112 * 48 * 4 + 8 * 16 * 112 * 4)   // 78848
__global__ __launch_bounds__(256, 2)
void rel_mma_kernel(const float* __restrict__ relh,
                    const float* __restrict__ relw)
{
    extern __shared__ u32 shm[];
    u32*   sRt = shm;                        // [112][48]
    float* sE  = (float*)(shm + 112 * 48);   // per-warp [16][112]

    int bid  = blockIdx.x;
    int bh   = bid >> 1, half = bid & 1;
    int b    = bh >> 1, head = bh & 1;
    int tid  = threadIdx.x;
    int warp = tid >> 5, lane = tid & 31;
    int g = lane >> 2, t = lane & 3;

    for (int i = tid; i < 112 * 48; i += 256) {
        int n = i / 48, w = i - n * 48;
        float r0 = 0.f, r1 = 0.f;
        if (n < 55)       { r0 = relh[n * 96 + 2 * w];        r1 = relh[n * 96 + 2 * w + 1]; }
        else if (n < 110) { r0 = relw[(n - 55) * 96 + 2 * w]; r1 = relw[(n - 55) * 96 + 2 * w + 1]; }
        sRt[n * 48 + (w & 3) * 12 + (w >> 2)] = bf2(r0 * LOG2E, r1 * LOG2E);
    }
    __syncthreads();

    const float* qbase = g_qp + (size_t)b * NQ * COUT + head * HDIM;
    float* myE = sE + warp * (16 * 112);
    int mEnd = (half == 0) ? 25 : 49;

    for (int m = half * 25 + warp; m < mEnd; m += 8) {
        int s0 = m * 16 + g;
        const float* q0 = qbase + (size_t)(s0 + 1) * COUT;
        const float* q1 = qbase + (size_t)(s0 + 9) * COUT;

        u32 a[6][4];
        #pragma unroll
        for (int ks = 0; ks < 6; ks++) {
            float2 x0 = *(const float2*)(q0 + 16 * ks + 2 * t);
            float2 x1 = *(const float2*)(q1 + 16 * ks + 2 * t);
            float2 x2 = *(const float2*)(q0 + 16 * ks + 2 * t + 8);
            float2 x3 = *(const float2*)(q1 + 16 * ks + 2 * t + 8);
            a[ks][0] = bf2(x0.x, x0.y);
            a[ks][1] = bf2(x1.x, x1.y);
            a[ks][2] = bf2(x2.x, x2.y);
            a[ks][3] = bf2(x3.x, x3.y);
        }

        #pragma unroll
        for (int nt = 0; nt < 14; nt++) {
            const uint4* rp = (const uint4*)(sRt + (8 * nt + g) * 48) + t * 3;
            uint4 R0 = rp[0], R1 = rp[1], R2 = rp[2];
            float acc[4] = {0.f, 0.f, 0.f, 0.f};
            mma_bf16(acc, a[0], R0.x, R0.y); mma_bf16(acc, a[1], R0.z, R0.w);
            mma_bf16(acc, a[2], R1.x, R1.y); mma_bf16(acc, a[3], R1.z, R1.w);
            mma_bf16(acc, a[4], R2.x, R2.y); mma_bf16(acc, a[5], R2.z, R2.w);
            *(float2*)(myE + g * 112 + 8 * nt + 2 * t)       = make_float2(acc[0], acc[1]);
            *(float2*)(myE + (g + 8) * 112 + 8 * nt + 2 * t) = make_float2(acc[2], acc[3]);
        }
        __syncwarp();

        int sbase = m * 16;
        float* outp = g_ehw + ((size_t)bh * 784 + sbase) * 28;
        #pragma unroll
        for (int it = 0; it < 14; it++) {
            int idx = lane + 32 * it;
            int r = idx / 28, k = idx - r * 28;
            int s = sbase + r;
            int qy = s / 28, qx = s - qy * 28;
            int col = (k < 14) ? (qy - 2 * k + 26) : (55 + qx - 2 * (k - 14) + 26);
            outp[idx] = myE[r * 112 + col];
        }
        __syncwarp();
    }
}

// =====================================================================
// Kernel D: fused attention — round-11 version (unchanged).
// =====================================================================
#define SK_OFF   0
#define SVT_OFF  54400
#define ATTN_SMEM 98944

__global__ __launch_bounds__(512, 1)
void attn_kernel(float* __restrict__ out)
{
    extern __shared__ char smem[];
    u32* sK32 = (u32*)(smem + SK_OFF);
    u32* sV32 = (u32*)(smem + SVT_OFF);
    int bh   = blockIdx.x;
    int b    = bh >> 1, head = bh & 1;
    int tid  = threadIdx.x;
    int warp = tid >> 5, lane = tid & 31;
    int g = lane >> 2, t = lane & 3;

    const float SC2 = SCALE * LOG2E;

    for (int i = tid; i < 200 * 64; i += 512) {
        int j = i >> 6, c2 = i & 63;
        u32 val = 0;
        if (j < NK) {
            if (c2 < 48) {
                const float* kp = g_kp + ((size_t)b * NK + j) * COUT + head * HDIM + 2 * c2;
                val = bf2(SC2 * kp[0], SC2 * kp[1]);
            } else if (j >= 1) {
                int ky = (j - 1) / 14, kx = (j - 1) - 14 * ky;
                int i0 = 2 * (c2 - 48);
                int i1 = i0 + 1;
                bool lo = (i0 < 14) ? (i0 == ky) : ((i0 < 28) && (i0 - 14 == kx));
                bool hi = (i1 < 14) ? (i1 == ky) : ((i1 < 28) && (i1 - 14 == kx));
                val = (lo ? 0x3F80u : 0u) | (hi ? 0x3F800000u : 0u);
            }
        }
        sK32[j * 68 + (c2 & 3) * 16 + (c2 >> 2)] = val;
    }
    for (int i = tid; i < 108 * 96; i += 512) {
        int w = i / 96, c = i - w * 96;
        int j0 = 2 * w;
        const float* vp = g_vp + ((size_t)b * NK + j0) * COUT + head * HDIM + c;
        float v0 = (j0     < NK) ? vp[0]    : 0.f;
        float v1 = (j0 + 1 < NK) ? vp[COUT] : 0.f;
        sV32[c * 116 + (w & 3) * 28 + (w >> 2)] = bf2(v0, v1);
    }
    __syncthreads();

    const float* qbase = g_qp + (size_t)b * NQ * COUT + head * HDIM;
    const float* ebase = g_ehw + (size_t)bh * 784 * 28;

    for (int tile = warp; tile < 50; tile += 16) {
        int q0 = tile * 16;
        int r0 = q0 + g, r1 = r0 + 8;
        int r0c = (r0 < NQ) ? r0 : NQ - 1;
        int r1c = (r1 < NQ) ? r1 : NQ - 1;

        const float* q_r0 = qbase + (size_t)r0c * COUT;
        const float* q_r1 = qbase + (size_t)r1c * COUT;
        u32 a[8][4];
        #pragma unroll
        for (int ks = 0; ks < 6; ks++) {
            float2 x0 = *(const float2*)(q_r0 + 16 * ks + 2 * t);
            float2 x1 = *(const float2*)(q_r1 + 16 * ks + 2 * t);
            float2 x2 = *(const float2*)(q_r0 + 16 * ks + 2 * t + 8);
            float2 x3 = *(const float2*)(q_r1 + 16 * ks + 2 * t + 8);
            a[ks][0] = bf2(x0.x, x0.y);
            a[ks][1] = bf2(x1.x, x1.y);
            a[ks][2] = bf2(x2.x, x2.y);
            a[ks][3] = bf2(x3.x, x3.y);
        }
        {
            bool v0ok = (r0 >= 1 && r0 < NQ);
            bool v1ok = (r1 >= 1 && r1 < NQ);
            const float* e0p = ebase + (size_t)(v0ok ? r0 - 1 : 0) * 28;
            const float* e1p = ebase + (size_t)(v1ok ? r1 - 1 : 0) * 28;
            float2 h;
            h = *(const float2*)(e0p + 2 * t);       a[6][0] = v0ok ? bf2(h.x, h.y) : 0u;
            h = *(const float2*)(e1p + 2 * t);       a[6][1] = v1ok ? bf2(h.x, h.y) : 0u;
            h = *(const float2*)(e0p + 8 + 2 * t);   a[6][2] = v0ok ? bf2(h.x, h.y) : 0u;
            h = *(const float2*)(e1p + 8 + 2 * t);   a[6][3] = v1ok ? bf2(h.x, h.y) : 0u;
            h = *(const float2*)(e0p + 16 + 2 * t);  a[7][0] = v0ok ? bf2(h.x, h.y) : 0u;
            h = *(const float2*)(e1p + 16 + 2 * t);  a[7][1] = v1ok ? bf2(h.x, h.y) : 0u;
            if (t < 2) {
                h = *(const float2*)(e0p + 24 + 2 * t); a[7][2] = v0ok ? bf2(h.x, h.y) : 0u;
                h = *(const float2*)(e1p + 24 + 2 * t); a[7][3] = v1ok ? bf2(h.x, h.y) : 0u;
            } else { a[7][2] = 0u; a[7][3] = 0u; }
        }

        float o[12][4];
        #pragma unroll
        for (int nt = 0; nt < 12; nt++)
            #pragma unroll
            for (int i = 0; i < 4; i++) o[nt][i] = 0.f;
        float slo = 0.f, shi = 0.f;

        #pragma unroll
        for (int ch = 0; ch < 6; ch++) {
            float acc[4][4];
            #pragma unroll
            for (int nt = 0; nt < 4; nt++)
                #pragma unroll
                for (int i = 0; i < 4; i++) acc[nt][i] = 0.f;

            #pragma unroll
            for (int nt2 = 0; nt2 < 4; nt2++) {
                int nt = 4 * ch + nt2;
                const uint4* kp = (const uint4*)(sK32 + (8 * nt + g) * 68 + t * 16);
                uint4 K0 = kp[0], K1 = kp[1], K2 = kp[2], K3 = kp[3];
                float* d = acc[nt2];
                mma_bf16(d, a[0], K0.x, K0.y); mma_bf16(d, a[1], K0.z, K0.w);
                mma_bf16(d, a[2], K1.x, K1.y); mma_bf16(d, a[3], K1.z, K1.w);
                mma_bf16(d, a[4], K2.x, K2.y); mma_bf16(d, a[5], K2.z, K2.w);
                mma_bf16(d, a[6], K3.x, K3.y); mma_bf16(d, a[7], K3.z, K3.w);
            }

            u32 pa[2][4];
            #pragma unroll
            for (int ks2 = 0; ks2 < 2; ks2++) {
                float e00 = ex2(acc[2 * ks2][0]),     e01 = ex2(acc[2 * ks2][1]);
                float e02 = ex2(acc[2 * ks2][2]),     e03 = ex2(acc[2 * ks2][3]);
                float e10 = ex2(acc[2 * ks2 + 1][0]), e11 = ex2(acc[2 * ks2 + 1][1]);
                float e12 = ex2(acc[2 * ks2 + 1][2]), e13 = ex2(acc[2 * ks2 + 1][3]);
                slo += e00 + e01 + e10 + e11;
                shi += e02 + e03 + e12 + e13;
                pa[ks2][0] = bf2(e00, e01); pa[ks2][1] = bf2(e02, e03);
                pa[ks2][2] = bf2(e10, e11); pa[ks2][3] = bf2(e12, e13);
            }

            #pragma unroll
            for (int nt = 0; nt < 12; nt++) {
                const uint4* vp = (const uint4*)(sV32 + (8 * nt + g) * 116 + t * 28 + ch * 4);
                uint4 V = vp[0];
                float* d = o[nt];
                mma_bf16(d, pa[0], V.x, V.y);
                mma_bf16(d, pa[1], V.z, V.w);
            }
        }

        {
            float at[4] = {0.f, 0.f, 0.f, 0.f};
            const uint4* kp = (const uint4*)(sK32 + (192 + g) * 68 + t * 16);
            uint4 K0 = kp[0], K1 = kp[1], K2 = kp[2], K3 = kp[3];
            mma_bf16(at, a[0], K0.x, K0.y); mma_bf16(at, a[1], K0.z, K0.w);
            mma_bf16(at, a[2], K1.x, K1.y); mma_bf16(at, a[3], K1.z, K1.w);
            mma_bf16(at, a[4], K2.x, K2.y); mma_bf16(at, a[5], K2.z, K2.w);
            mma_bf16(at, a[6], K3.x, K3.y); mma_bf16(at, a[7], K3.z, K3.w);
            int j0 = 192 + 2 * t;
            float e0 = (j0     < NK) ? ex2(at[0]) : 0.f;
            float e1 = (j0 + 1 < NK) ? ex2(at[1]) : 0.f;
            float e2 = (j0     < NK) ? ex2(at[2]) : 0.f;
            float e3 = (j0 + 1 < NK) ? ex2(at[3]) : 0.f;
            slo += e0 + e1; shi += e2 + e3;
            u32 paT[4] = { bf2(e0, e1), bf2(e2, e3), 0u, 0u };
            #pragma unroll
            for (int nt = 0; nt < 12; nt++) {
                uint4 V = *(const uint4*)(sV32 + (8 * nt + g) * 116 + t * 28 + 24);
                mma_bf16(o[nt], paT, V.x, V.y);
            }
        }

        slo += __shfl_xor_sync(0xffffffffu, slo, 1);
        slo += __shfl_xor_sync(0xffffffffu, slo, 2);
        shi += __shfl_xor_sync(0xffffffffu, shi, 1);
        shi += __shfl_xor_sync(0xffffffffu, shi, 2);
        float ilo = 1.f / slo, ihi = 1.f / shi;

        float* obase = out + (size_t)b * NQ * COUT + head * HDIM;
        #pragma unroll
        for (int nt = 0; nt < 12; nt++) {
            int c = 8 * nt + 2 * t;
            if (r0 < NQ) {
                float2 r = make_float2(o[nt][0] * ilo, o[nt][1] * ilo);
                if (r0 >= 1) {
                    float2 q = *(const float2*)(qbase + (size_t)r0 * COUT + c);
                    r.x += q.x; r.y += q.y;
                }
                *(float2*)(obase + (size_t)r0 * COUT + c) = r;
            }
            if (r1 < NQ) {
                float2 r = make_float2(o[nt][2] * ihi, o[nt][3] * ihi);
                if (r1 >= 1) {
                    float2 q = *(const float2*)(qbase + (size_t)r1 * COUT + c);
                    r.x += q.x; r.y += q.y;
                }
                *(float2*)(obase + (size_t)r1 * COUT + c) = r;
            }
        }
    }
}

// =====================================================================
// launch: pre -> proj -> rel -> attn
// =====================================================================
extern "C" void kernel_launch(void* const* d_in, const int* in_sizes, int n_in,
                              void* d_out, int out_size)
{
    const float* hs    = (const float*)d_in[0];
    const float* Wq    = (const float*)d_in[1];
    const float* bq    = (const float*)d_in[2];
    const float* Wk    = (const float*)d_in[3];
    const float* bk    = (const float*)d_in[4];
    const float* Wv    = (const float*)d_in[5];
    const float* bv    = (const float*)d_in[6];
    const float* pqw   = (const float*)d_in[7];
    const float* pkw   = (const float*)d_in[8];
    const float* pvw   = (const float*)d_in[9];
    const float* gq    = (const float*)d_in[10];
    const float* betaq = (const float*)d_in[11];
    const float* gk    = (const float*)d_in[12];
    const float* betak = (const float*)d_in[13];
    const float* gv    = (const float*)d_in[14];
    const float* betav = (const float*)d_in[15];
    const float* relh  = (const float*)d_in[16];
    const float* relw  = (const float*)d_in[17];
    float* out = (float*)d_out;

    cudaFuncSetAttribute(proj_mma_kernel, cudaFuncAttributeMaxDynamicSharedMemorySize, PROJ_SMEM);
    cudaFuncSetAttribute(rel_mma_kernel, cudaFuncAttributeMaxDynamicSharedMemorySize, RELN_SMEM);
    cudaFuncSetAttribute(attn_kernel,  cudaFuncAttributeMaxDynamicSharedMemorySize, ATTN_SMEM);

    // A: q pools + fused kv pools + weight split
    pre_kernel<<<QPB + KPB + 3, 256>>>(hs,
        pqw, gq, betaq, pkw, gk, betak, pvw, gv, betav, Wq, Wk, Wv);

    // B: all three projections (256 rows/block)
    proj_mma_kernel<<<QJB + 2 * KJB, 256, PROJ_SMEM>>>(bq, bk, bv);

    // C: rel-pos bias via tensor cores
    rel_mma_kernel<<<BATCH * NHEAD * 2, 256, RELN_SMEM>>>(relh, relw);

    // D: fused tensor-core attention
    attn_kernel<<<BATCH * NHEAD, 512, ATTN_SMEM>>>(out);
}